// round 7
// baseline (speedup 1.0000x reference)
#include <cuda_runtime.h>
#include <cuda_fp16.h>
#include <mma.h>

using namespace nvcuda;

// Dims: B=8, N=128, D=256. BN_rows = 1024. M_edge = B*N*N = 131072.

// ---------------- static scratch (no allocations allowed) -------------------
__device__ __half g_e1[(size_t)131072 * 512];   // [m, 0:256]=e1_fuse, [256:512]=e1_fc
__device__ __half g_e2[(size_t)131072 * 512];
__device__ __half g_Wedge1[256 * 512];
__device__ __half g_Wedge2[256 * 512];
__device__ __half g_Wproj[256 * 1536];          // cols: a1|b1|a2|b2|u1|u2
__device__ __half g_Wfc3[512 * 256];
__device__ __half g_Wweight[256 * 256];
__device__ __half g_text_h[1024 * 256];
__device__ __half g_out_h[1024 * 256];
__device__ __half g_proj_h[1024 * 1536];
__device__ __half g_acc_h[1024 * 512];
__device__ float  g_out[1024 * 256];
__device__ float  g_gcn[1024 * 256];
__device__ float  g_ta[1024 * 256];

__device__ __forceinline__ unsigned smem_u32(const void* p) {
    return (unsigned)__cvta_generic_to_shared(p);
}
#define CPA16(dst, src) asm volatile("cp.async.cg.shared.global [%0], [%1], 16;" :: "r"(dst), "l"(src))
#define CPA_COMMIT() asm volatile("cp.async.commit_group;")
#define CPA_WAIT0()  asm volatile("cp.async.wait_group 0;" ::: "memory")

__device__ __forceinline__ void unpack8(uint4 v, float* f) {
    const __half2* h = reinterpret_cast<const __half2*>(&v);
#pragma unroll
    for (int e = 0; e < 4; e++) {
        float2 t = __half22float2(h[e]);
        f[2 * e] = t.x; f[2 * e + 1] = t.y;
    }
}

// ---------------------------------------------------------------------------
// prep: pack fp16 weight layouts + fp16 text
// ---------------------------------------------------------------------------
__global__ __launch_bounds__(256) void prep_kernel(
    const float* __restrict__ fuse1_w, const float* __restrict__ fuse2_w,
    const float* __restrict__ fc1_w0,  const float* __restrict__ fc2_w0,
    const float* __restrict__ fc3_w,   const float* __restrict__ weight,
    const float* __restrict__ text)
{
    const int TOTAL = 131072 + 131072 + 393216 + 131072 + 65536 + 262144;
    for (int idx = blockIdx.x * 256 + threadIdx.x; idx < TOTAL; idx += gridDim.x * 256) {
        int t = idx;
        if (t < 131072) {
            int k = t >> 9, n = t & 511;
            float v = (n < 256) ? fuse1_w[(256 + k) * 256 + n]
                                : fc1_w0[(512 + k) * 256 + (n - 256)];
            g_Wedge1[t] = __float2half_rn(v);
        } else if ((t -= 131072) < 131072) {
            int k = t >> 9, n = t & 511;
            float v = (n < 256) ? fuse2_w[(256 + k) * 256 + n]
                                : fc2_w0[(512 + k) * 256 + (n - 256)];
            g_Wedge2[t] = __float2half_rn(v);
        } else if ((t -= 131072) < 393216) {
            int k = t / 1536, n = t % 1536;
            int seg = n >> 8, c = n & 255;
            float v;
            switch (seg) {
                case 0:  v = fc1_w0[k * 256 + c]; break;
                case 1:  v = fc1_w0[(256 + k) * 256 + c]; break;
                case 2:  v = fc2_w0[k * 256 + c]; break;
                case 3:  v = fc2_w0[(256 + k) * 256 + c]; break;
                case 4:  v = fuse1_w[k * 256 + c]; break;
                default: v = fuse2_w[k * 256 + c]; break;
            }
            g_Wproj[t] = __float2half_rn(v);
        } else if ((t -= 393216) < 131072) {
            g_Wfc3[t] = __float2half_rn(fc3_w[t]);
        } else if ((t -= 131072) < 65536) {
            g_Wweight[t] = __float2half_rn(weight[t]);
        } else {
            t -= 65536;
            g_text_h[t] = __float2half_rn(text[t]);
        }
    }
}

// ---------------------------------------------------------------------------
// cp.async-pipelined wmma GEMM: C[M,N] = A[M,K] @ B[K,N] (row-major).
// 2 smem stages; per K-step: [STS A (f32 path)] -> wait -> sync -> issue next
// (cp.async, no registers) -> mma. One barrier per step, race-free.
// MODE 0/1: edge1/edge2 (A fp32 ext), K=256, NW=512, BN=256
// MODE 2:   text_h @ Wweight -> relu -> g_out+g_out_h, K=256, NW=256, BN=256
// MODE 3:   out_h @ Wproj -> g_proj_h, K=256, NW=1536, BN=256
// MODE 4:   acc_h @ Wfc3 -> g_gcn, K=512, NW=256, BN=64
// ---------------------------------------------------------------------------
template <int MODE>
__global__ __launch_bounds__(256) void gemm_kernel(const float* __restrict__ Af)
{
    constexpr bool A_F32 = (MODE <= 1);
    constexpr int K  = (MODE == 4) ? 512 : 256;
    constexpr int NW = (MODE <= 1) ? 512 : (MODE == 3 ? 1536 : 256);
    constexpr int BN = (MODE == 4) ? 64 : 256;
    constexpr int BM = 64, BK = 32;
    constexpr int KSTEPS = K / BK;
    constexpr int WNF = BN / 64;                 // B frags per warp
    constexpr int LDA = BK + 8;                  // 40 halves (80B rows, 16B-aligned)
    constexpr int LDB = BN + 8;
    constexpr int AS_H = BM * LDA;
    constexpr int BS_H = BK * LDB;
    constexpr int STG = AS_H + BS_H;             // halves per stage
    constexpr int NB16 = (BK * BN / 8) / 256;    // cp.async(16B) per thread for B
    constexpr int BROW = BN / 8;                 // 16B chunks per B row
    constexpr int EPIL = 32 * BN * 4;
    constexpr int SMB = (2 * STG * 2 > EPIL) ? 2 * STG * 2 : EPIL;

    __shared__ __align__(16) char smem[SMB];
    __half* As0 = reinterpret_cast<__half*>(smem);
    __half* As1 = As0 + STG;
    __half* Bs0 = As0 + AS_H;
    __half* Bs1 = As1 + AS_H;
    float*  sC  = reinterpret_cast<float*>(smem);

    const __half* Bg =
        (MODE == 0) ? g_Wedge1 : (MODE == 1) ? g_Wedge2 :
        (MODE == 2) ? g_Wweight : (MODE == 3) ? g_Wproj : g_Wfc3;
    const __half* Ah =
        (MODE == 2) ? g_text_h : (MODE == 3) ? g_out_h : g_acc_h;

    const int n0 = blockIdx.x * BN;
    const int m0 = blockIdx.y * BM;
    const int tid = threadIdx.x;
    const int wid = tid >> 5;
    const int wm = wid >> 2, wn = wid & 3;

    const unsigned sA[2] = { smem_u32(As0), smem_u32(As1) };
    const unsigned sB[2] = { smem_u32(Bs0), smem_u32(Bs1) };

    wmma::fragment<wmma::accumulator, 16, 16, 16, float> acc[2][WNF];
#pragma unroll
    for (int i = 0; i < 2; i++)
#pragma unroll
        for (int j = 0; j < WNF; j++) wmma::fill_fragment(acc[i][j], 0.0f);

    float4 raf[2];
    // per-thread fixed indices
    const int ar = tid >> 3, ac4 = (tid & 7) * 4;       // f32 A staging (2 rounds)
    const int ahr = tid >> 2, ahc = (tid & 3) * 8;      // half A cp.async

    // ---- preload stage 0 ----
    if (A_F32) {
#pragma unroll
        for (int r = 0; r < 2; r++) {
            int row = ar + r * 32;
            raf[r] = *reinterpret_cast<const float4*>(Af + (size_t)(m0 + row) * K + ac4);
        }
    } else {
        CPA16(sA[0] + (unsigned)(ahr * LDA + ahc) * 2,
              Ah + (size_t)(m0 + ahr) * K + ahc);
    }
#pragma unroll
    for (int r = 0; r < NB16; r++) {
        int idx = tid + r * 256;
        int row = idx / BROW, c = idx % BROW;
        CPA16(sB[0] + (unsigned)(row * LDB + c * 8) * 2,
              Bg + (size_t)row * NW + n0 + c * 8);
    }
    CPA_COMMIT();

    for (int ks = 0; ks < KSTEPS; ks++) {
        const int p = ks & 1;
        const __half* Asm = p ? As1 : As0;
        const __half* Bsm = p ? Bs1 : Bs0;

        if (A_F32) {   // stage p's A from regs -> smem (visible after the sync)
            __half* Aw = const_cast<__half*>(Asm);
#pragma unroll
            for (int r = 0; r < 2; r++) {
                int row = ar + r * 32;
                __half hx[4] = {__float2half_rn(raf[r].x), __float2half_rn(raf[r].y),
                                __float2half_rn(raf[r].z), __float2half_rn(raf[r].w)};
                *reinterpret_cast<uint2*>(Aw + row * LDA + ac4) =
                    *reinterpret_cast<uint2*>(hx);
            }
        }
        CPA_WAIT0();
        __syncthreads();

        if (ks + 1 < KSTEPS) {   // issue next stage (post-sync: buffer is free)
            const int k0n = (ks + 1) * BK;
            const unsigned sAn = sA[p ^ 1], sBn = sB[p ^ 1];
            if (A_F32) {
#pragma unroll
                for (int r = 0; r < 2; r++) {
                    int row = ar + r * 32;
                    raf[r] = *reinterpret_cast<const float4*>(
                        Af + (size_t)(m0 + row) * K + k0n + ac4);
                }
            } else {
                CPA16(sAn + (unsigned)(ahr * LDA + ahc) * 2,
                      Ah + (size_t)(m0 + ahr) * K + k0n + ahc);
            }
#pragma unroll
            for (int r = 0; r < NB16; r++) {
                int idx = tid + r * 256;
                int row = idx / BROW, c = idx % BROW;
                CPA16(sBn + (unsigned)(row * LDB + c * 8) * 2,
                      Bg + (size_t)(k0n + row) * NW + n0 + c * 8);
            }
            CPA_COMMIT();
        }

        // ---- mma on stage p ----
#pragma unroll
        for (int kk = 0; kk < BK; kk += 16) {
            wmma::fragment<wmma::matrix_a, 16, 16, 16, half, wmma::row_major> af[2];
            wmma::fragment<wmma::matrix_b, 16, 16, 16, half, wmma::row_major> bf[WNF];
#pragma unroll
            for (int i = 0; i < 2; i++)
                wmma::load_matrix_sync(af[i], Asm + (wm * 32 + i * 16) * LDA + kk, LDA);
#pragma unroll
            for (int j = 0; j < WNF; j++)
                wmma::load_matrix_sync(bf[j], Bsm + kk * LDB + wn * (BN / 4) + j * 16, LDB);
#pragma unroll
            for (int i = 0; i < 2; i++)
#pragma unroll
                for (int j = 0; j < WNF; j++)
                    wmma::mma_sync(acc[i][j], af[i], bf[j], acc[i][j]);
        }
    }

    // ---- epilogue: 2 passes of 32 rows via sC ----
#pragma unroll
    for (int pass = 0; pass < 2; pass++) {
        __syncthreads();
        if (wm == pass) {
#pragma unroll
            for (int i = 0; i < 2; i++)
#pragma unroll
                for (int j = 0; j < WNF; j++)
                    wmma::store_matrix_sync(&sC[(i * 16) * BN + wn * (BN / 4) + j * 16],
                                            acc[i][j], BN, wmma::mem_row_major);
        }
        __syncthreads();
        int rbase = m0 + pass * 32;
        if constexpr (MODE <= 1 || MODE == 3) {
            __half* C = (MODE == 0) ? g_e1 : (MODE == 1) ? g_e2 : g_proj_h;
#pragma unroll
            for (int r = 0; r < (32 * BN / 2) / 256; r++) {
                int idx = tid + r * 256;
                int row = idx / (BN / 2), c2 = (idx % (BN / 2)) * 2;
                __half2 hv = __floats2half2_rn(sC[row * BN + c2], sC[row * BN + c2 + 1]);
                *reinterpret_cast<__half2*>(C + (size_t)(rbase + row) * NW + n0 + c2) = hv;
            }
        } else if constexpr (MODE == 2) {
#pragma unroll
            for (int r = 0; r < 8; r++) {
                int idx = tid + r * 256;
                int row = idx >> 6, c4 = (idx & 63) * 4;
                float4 v = *reinterpret_cast<const float4*>(&sC[row * BN + c4]);
                v.x = fmaxf(v.x, 0.f); v.y = fmaxf(v.y, 0.f);
                v.z = fmaxf(v.z, 0.f); v.w = fmaxf(v.w, 0.f);
                size_t o = (size_t)(rbase + row) * 256 + c4;
                *reinterpret_cast<float4*>(g_out + o) = v;
                *reinterpret_cast<__half2*>(g_out_h + o)     = __floats2half2_rn(v.x, v.y);
                *reinterpret_cast<__half2*>(g_out_h + o + 2) = __floats2half2_rn(v.z, v.w);
            }
        } else { // MODE 4
#pragma unroll
            for (int r = 0; r < (32 * BN / 4) / 256; r++) {
                int idx = tid + r * 256;
                int row = idx / (BN / 4), c4 = (idx % (BN / 4)) * 4;
                *reinterpret_cast<float4*>(g_gcn + (size_t)(rbase + row) * 256 + n0 + c4) =
                    *reinterpret_cast<const float4*>(&sC[row * BN + c4]);
            }
        }
    }
}

// ---------------------------------------------------------------------------
// ta = text @ align_lin (fp32; precision-critical for softmax logits)
// ---------------------------------------------------------------------------
__global__ __launch_bounds__(256) void ta_kernel(const float* __restrict__ text,
                                                 const float* __restrict__ alin)
{
    __shared__ float sT[8][260];
    const int r0 = blockIdx.x * 8;
    for (int idx = threadIdx.x; idx < 8 * 64; idx += 256) {
        int r = idx >> 6, c4 = (idx & 63) * 4;
        *reinterpret_cast<float4*>(&sT[r][c4]) =
            *reinterpret_cast<const float4*>(text + (size_t)(r0 + r) * 256 + c4);
    }
    __syncthreads();
    const int n = threadIdx.x;
    float acc[8];
#pragma unroll
    for (int r = 0; r < 8; r++) acc[r] = 0.f;
    for (int k = 0; k < 256; k += 4) {
        float a0 = alin[(size_t)k * 256 + n];
        float a1 = alin[(size_t)(k + 1) * 256 + n];
        float a2 = alin[(size_t)(k + 2) * 256 + n];
        float a3 = alin[(size_t)(k + 3) * 256 + n];
#pragma unroll
        for (int r = 0; r < 8; r++) {
            float4 t = *reinterpret_cast<const float4*>(&sT[r][k]);
            acc[r] += t.x * a0 + t.y * a1 + t.z * a2 + t.w * a3;
        }
    }
#pragma unroll
    for (int r = 0; r < 8; r++)
        g_ta[(size_t)(r0 + r) * 256 + n] = acc[r];
}

// ---------------------------------------------------------------------------
// Self-alignment attention (fp32): block per (b,i)
// ---------------------------------------------------------------------------
__global__ __launch_bounds__(256) void attn_kernel(const float* __restrict__ text,
                                                   const float* __restrict__ tmask,
                                                   const float* __restrict__ align_bias,
                                                   float* __restrict__ outp)
{
    __shared__ float slog[128];
    __shared__ float s_red[2];
    const int row = blockIdx.x;
    const int b = row >> 7;
    const int tid = threadIdx.x, w = tid >> 5, lane = tid & 31;

    float ta0[8];
    {
        const float* tarow = g_ta + (size_t)row * 256 + lane * 8;
        float4 q0 = *reinterpret_cast<const float4*>(tarow);
        float4 q1 = *reinterpret_cast<const float4*>(tarow + 4);
        ta0[0] = q0.x; ta0[1] = q0.y; ta0[2] = q0.z; ta0[3] = q0.w;
        ta0[4] = q1.x; ta0[5] = q1.y; ta0[6] = q1.z; ta0[7] = q1.w;
    }
    for (int j = w; j < 128; j += 8) {
        const float* tr = text + (size_t)(b * 128 + j) * 256 + lane * 8;
        float4 t0 = *reinterpret_cast<const float4*>(tr);
        float4 t1 = *reinterpret_cast<const float4*>(tr + 4);
        float d = ta0[0] * t0.x + ta0[1] * t0.y + ta0[2] * t0.z + ta0[3] * t0.w
                + ta0[4] * t1.x + ta0[5] * t1.y + ta0[6] * t1.z + ta0[7] * t1.w;
#pragma unroll
        for (int o = 16; o > 0; o >>= 1) d += __shfl_xor_sync(0xffffffffu, d, o);
        if (lane == 0)
            slog[j] = d + (1.0f - tmask[b * 128 + j]) * -1e20f;
    }
    __syncthreads();
    if (w == 0) {
        float m = fmaxf(fmaxf(slog[lane], slog[lane + 32]),
                        fmaxf(slog[lane + 64], slog[lane + 96]));
#pragma unroll
        for (int o = 16; o > 0; o >>= 1) m = fmaxf(m, __shfl_xor_sync(0xffffffffu, m, o));
        if (lane == 0) s_red[0] = m;
    }
    __syncthreads();
    float smax = s_red[0];
    if (tid < 128) slog[tid] = expf(slog[tid] - smax);
    __syncthreads();
    if (w == 0) {
        float s = slog[lane] + slog[lane + 32] + slog[lane + 64] + slog[lane + 96];
#pragma unroll
        for (int o = 16; o > 0; o >>= 1) s += __shfl_xor_sync(0xffffffffu, s, o);
        if (lane == 0) s_red[1] = s;
    }
    __syncthreads();
    float inv = 1.0f / s_red[1];
    const int c = tid;
    float acc = 0.f;
    for (int j = 0; j < 128; j++)
        acc += slog[j] * text[(size_t)(b * 128 + j) * 256 + c];
    outp[262144 + (size_t)row * 256 + c] = acc * inv * tmask[row] + align_bias[c];
}

// ---------------------------------------------------------------------------
// Gate/accumulate: block per (b,i), warp per j (16 j's each of 8 warps).
// ---------------------------------------------------------------------------
__global__ __launch_bounds__(256) void accum_kernel(
    const float* __restrict__ adj1, const float* __restrict__ adj2,
    const float* __restrict__ w1g,  const float* __restrict__ w2g,
    const float* __restrict__ b1g,  const float* __restrict__ b2g)
{
    __shared__ float s1[8][256];
    __shared__ float s2[8][256];
    __shared__ float sadj[8][2];
    const int row = blockIdx.x;             // b*128 + i
    const int b = row >> 7;
    const int tid = threadIdx.x, w = tid >> 5, lane = tid & 31;
    const int cbase = lane * 8;

    float a1[8], a2[8], w1[8], w2[8], acc1[8], acc2[8];
    {
        const __half* ph = g_proj_h + (size_t)row * 1536;
        uint4 ua = *reinterpret_cast<const uint4*>(ph + cbase);
        uint4 ub = *reinterpret_cast<const uint4*>(ph + 512 + cbase);
        unpack8(ua, a1); unpack8(ub, a2);
    }
#pragma unroll
    for (int k = 0; k < 8; k++) {
        w1[k] = w1g[cbase + k]; w2[k] = w2g[cbase + k];
        acc1[k] = 0.f; acc2[k] = 0.f;
    }
    const float fb1 = b1g[0], fb2 = b2g[0];
    float as1 = 0.f, as2 = 0.f;

    for (int j = w; j < 128; j += 8) {
        const __half* e1p = g_e1 + ((size_t)row * 128 + j) * 512;
        const __half* e2p = g_e2 + ((size_t)row * 128 + j) * 512;
        const __half* pj  = g_proj_h + (size_t)(b * 128 + j) * 1536;
        uint4 uf1 = *reinterpret_cast<const uint4*>(e1p + cbase);
        uint4 uc1 = *reinterpret_cast<const uint4*>(e1p + 256 + cbase);
        uint4 uf2 = *reinterpret_cast<const uint4*>(e2p + cbase);
        uint4 uc2 = *reinterpret_cast<const uint4*>(e2p + 256 + cbase);
        uint4 ub1 = *reinterpret_cast<const uint4*>(pj + 256 + cbase);
        uint4 ub2 = *reinterpret_cast<const uint4*>(pj + 768 + cbase);
        uint4 uu1 = *reinterpret_cast<const uint4*>(pj + 1024 + cbase);
        uint4 uu2 = *reinterpret_cast<const uint4*>(pj + 1280 + cbase);
        float f1[8], c1[8], f2[8], c2[8], bb1[8], bb2[8], u1[8], u2[8];
        unpack8(uf1, f1); unpack8(uc1, c1);
        unpack8(uf2, f2); unpack8(uc2, c2);
        unpack8(ub1, bb1); unpack8(ub2, bb2);
        unpack8(uu1, u1);  unpack8(uu2, u2);

        float d1 = 0.f, d2 = 0.f;
#pragma unroll
        for (int k = 0; k < 8; k++) {
            d1 += w1[k] * fmaxf(a1[k] + bb1[k] + c1[k], 0.f);
            d2 += w2[k] * fmaxf(a2[k] + bb2[k] + c2[k], 0.f);
        }
#pragma unroll
        for (int o = 16; o > 0; o >>= 1) {
            d1 += __shfl_xor_sync(0xffffffffu, d1, o);
            d2 += __shfl_xor_sync(0xffffffffu, d2, o);
        }
        float av1 = adj1[(size_t)row * 128 + j];
        float av2 = adj2[(size_t)row * 128 + j];
        float g1 = av1 / (1.f + __expf(-(d1 + fb1)));
        float g2 = av2 / (1.f + __expf(-(d2 + fb2)));
        as1 += av1; as2 += av2;
#pragma unroll
        for (int k = 0; k < 8; k++) {
            acc1[k] += g1 * fmaxf(u1[k] + f1[k], 0.f);
            acc2[k] += g2 * fmaxf(u2[k] + f2[k], 0.f);
        }
    }
#pragma unroll
    for (int k = 0; k < 8; k++) {
        s1[w][cbase + k] = acc1[k];
        s2[w][cbase + k] = acc2[k];
    }
    if (lane == 0) { sadj[w][0] = as1; sadj[w][1] = as2; }
    __syncthreads();
    const int c = tid;
    float t1 = 0.f, t2 = 0.f, den1 = 1.f, den2 = 1.f;
#pragma unroll
    for (int ww = 0; ww < 8; ww++) {
        t1 += s1[ww][c]; t2 += s2[ww][c];
        den1 += sadj[ww][0]; den2 += sadj[ww][1];
    }
    g_acc_h[(size_t)row * 512 + c]       = __float2half_rn(t1 / den1);
    g_acc_h[(size_t)row * 512 + 256 + c] = __float2half_rn(t2 / den2);
}

// ---------------------------------------------------------------------------
// out = layernorm(relu(g_gcn) + out + bias); refresh g_out / g_out_h
// ---------------------------------------------------------------------------
__global__ __launch_bounds__(256) void ln_kernel(
    const float* __restrict__ bias, const float* __restrict__ gamma,
    const float* __restrict__ beta, float* __restrict__ outp, int final_it)
{
    __shared__ float s[8];
    const int row = blockIdx.x, c = threadIdx.x;
    const int w = c >> 5, lane = c & 31;
    float v = fmaxf(g_gcn[(size_t)row * 256 + c], 0.f)
            + g_out[(size_t)row * 256 + c] + bias[c];
    float t = v;
#pragma unroll
    for (int o = 16; o > 0; o >>= 1) t += __shfl_xor_sync(0xffffffffu, t, o);
    if (lane == 0) s[w] = t;
    __syncthreads();
    float m = 0.f;
#pragma unroll
    for (int i = 0; i < 8; i++) m += s[i];
    m *= (1.f / 256.f);
    __syncthreads();
    float d = v - m;
    t = d * d;
#pragma unroll
    for (int o = 16; o > 0; o >>= 1) t += __shfl_xor_sync(0xffffffffu, t, o);
    if (lane == 0) s[w] = t;
    __syncthreads();
    float var = 0.f;
#pragma unroll
    for (int i = 0; i < 8; i++) var += s[i];
    var *= (1.f / 256.f);
    float r = rsqrtf(var + 1e-5f);
    float o = d * r * gamma[c] + beta[c];
    g_out[(size_t)row * 256 + c] = o;
    g_out_h[(size_t)row * 256 + c] = __float2half_rn(o);
    if (final_it) outp[(size_t)row * 256 + c] = o;
}

// ---------------------------------------------------------------------------
extern "C" void kernel_launch(void* const* d_in, const int* in_sizes, int n_in,
                              void* d_out, int out_size)
{
    const float* text       = (const float*)d_in[0];
    const float* adj1       = (const float*)d_in[1];
    const float* adj2       = (const float*)d_in[2];
    const float* edge1      = (const float*)d_in[3];
    const float* edge2      = (const float*)d_in[4];
    const float* textmask   = (const float*)d_in[5];
    const float* weight     = (const float*)d_in[6];
    const float* bias       = (const float*)d_in[7];
    const float* gamma      = (const float*)d_in[8];
    const float* beta       = (const float*)d_in[9];
    const float* fuse1_w    = (const float*)d_in[10];
    const float* fuse2_w    = (const float*)d_in[11];
    const float* fc3_w      = (const float*)d_in[12];
    const float* fc1_w0     = (const float*)d_in[13];
    const float* fc1_w1     = (const float*)d_in[14];
    const float* fc1_b1     = (const float*)d_in[15];
    const float* fc2_w0     = (const float*)d_in[16];
    const float* fc2_w1     = (const float*)d_in[17];
    const float* fc2_b1     = (const float*)d_in[18];
    const float* align_lin  = (const float*)d_in[19];
    const float* align_bias = (const float*)d_in[20];
    float* outp = (float*)d_out;

    prep_kernel<<<1024, 256>>>(fuse1_w, fuse2_w, fc1_w0, fc2_w0, fc3_w, weight, text);

    // self-alignment path (independent)
    ta_kernel<<<128, 256>>>(text, align_lin);
    attn_kernel<<<1024, 256>>>(text, textmask, align_bias, outp);

    // edge projections
    gemm_kernel<0><<<dim3(2, 2048), 256>>>(edge1);
    gemm_kernel<1><<<dim3(2, 2048), 256>>>(edge2);

    // out = relu(text @ weight) (relu fused into epilogue)
    gemm_kernel<2><<<dim3(1, 16), 256>>>(nullptr);

    for (int it = 0; it < 3; it++) {
        gemm_kernel<3><<<dim3(6, 16), 256>>>(nullptr);
        accum_kernel<<<1024, 256>>>(adj1, adj2, fc1_w1, fc2_w1, fc1_b1, fc2_b1);
        gemm_kernel<4><<<dim3(4, 16), 256>>>(nullptr);
        ln_kernel<<<1024, 256>>>(bias, gamma, beta, outp, it == 2 ? 1 : 0);
    }
}

// round 8
// speedup vs baseline: 1.2727x; 1.2727x over previous
#include <cuda_runtime.h>
#include <cuda_fp16.h>
#include <mma.h>

using namespace nvcuda;

// Dims: B=8, N=128, D=256. BN_rows = 1024. M_edge = B*N*N = 131072.

// ---------------- static scratch (no allocations allowed) -------------------
__device__ __half g_e1[(size_t)131072 * 512];   // [m, 0:256]=e1_fuse, [256:512]=e1_fc
__device__ __half g_e2[(size_t)131072 * 512];
__device__ __half g_Wedge1[256 * 512];
__device__ __half g_Wedge2[256 * 512];
__device__ __half g_Wproj[256 * 1536];          // cols: a1|b1|a2|b2|u1|u2
__device__ __half g_Wfc3[512 * 256];
__device__ __half g_Wweight[256 * 256];
__device__ __half g_text_h[1024 * 256];
__device__ __half g_out_h[1024 * 256];
__device__ __half g_proj_h[1024 * 1536];
__device__ __half g_acc_h[1024 * 512];
__device__ float  g_out[1024 * 256];
__device__ float  g_gcn[1024 * 256];
__device__ float  g_ta[1024 * 256];

__device__ __forceinline__ unsigned smem_u32(const void* p) {
    return (unsigned)__cvta_generic_to_shared(p);
}
#define CPA16(dst, src) asm volatile("cp.async.cg.shared.global [%0], [%1], 16;" :: "r"(dst), "l"(src))
#define CPA_COMMIT() asm volatile("cp.async.commit_group;")
#define CPA_WAIT0()  asm volatile("cp.async.wait_group 0;" ::: "memory")

__device__ __forceinline__ void unpack8(uint4 v, float* f) {
    const __half2* h = reinterpret_cast<const __half2*>(&v);
#pragma unroll
    for (int e = 0; e < 4; e++) {
        float2 t = __half22float2(h[e]);
        f[2 * e] = t.x; f[2 * e + 1] = t.y;
    }
}

// ---------------------------------------------------------------------------
// prep: pack fp16 weight layouts + fp16 text
// ---------------------------------------------------------------------------
__global__ __launch_bounds__(256) void prep_kernel(
    const float* __restrict__ fuse1_w, const float* __restrict__ fuse2_w,
    const float* __restrict__ fc1_w0,  const float* __restrict__ fc2_w0,
    const float* __restrict__ fc3_w,   const float* __restrict__ weight,
    const float* __restrict__ text)
{
    const int TOTAL = 131072 + 131072 + 393216 + 131072 + 65536 + 262144;
    for (int idx = blockIdx.x * 256 + threadIdx.x; idx < TOTAL; idx += gridDim.x * 256) {
        int t = idx;
        if (t < 131072) {
            int k = t >> 9, n = t & 511;
            float v = (n < 256) ? fuse1_w[(256 + k) * 256 + n]
                                : fc1_w0[(512 + k) * 256 + (n - 256)];
            g_Wedge1[t] = __float2half_rn(v);
        } else if ((t -= 131072) < 131072) {
            int k = t >> 9, n = t & 511;
            float v = (n < 256) ? fuse2_w[(256 + k) * 256 + n]
                                : fc2_w0[(512 + k) * 256 + (n - 256)];
            g_Wedge2[t] = __float2half_rn(v);
        } else if ((t -= 131072) < 393216) {
            int k = t / 1536, n = t % 1536;
            int seg = n >> 8, c = n & 255;
            float v;
            switch (seg) {
                case 0:  v = fc1_w0[k * 256 + c]; break;
                case 1:  v = fc1_w0[(256 + k) * 256 + c]; break;
                case 2:  v = fc2_w0[k * 256 + c]; break;
                case 3:  v = fc2_w0[(256 + k) * 256 + c]; break;
                case 4:  v = fuse1_w[k * 256 + c]; break;
                default: v = fuse2_w[k * 256 + c]; break;
            }
            g_Wproj[t] = __float2half_rn(v);
        } else if ((t -= 393216) < 131072) {
            g_Wfc3[t] = __float2half_rn(fc3_w[t]);
        } else if ((t -= 131072) < 65536) {
            g_Wweight[t] = __float2half_rn(weight[t]);
        } else {
            t -= 65536;
            g_text_h[t] = __float2half_rn(text[t]);
        }
    }
}

// ---------------------------------------------------------------------------
// cp.async-pipelined wmma GEMM: C[M,N] = A[M,K] @ B[K,N] (row-major).
// 2 smem stages; per K-step: [STS A (f32 path)] -> wait -> sync -> issue next
// (cp.async, no registers) -> mma. One barrier per step, race-free.
// __launch_bounds__(256, 2): cap regs at 128 so 2 CTAs/SM stay resident
// (R7 evidence: 136 regs -> 1 CTA/SM -> occ 12.5%, 284us; the whole loss).
// MODE 0/1: edge1/edge2 (A fp32 ext), K=256, NW=512, BN=256
// MODE 2:   text_h @ Wweight -> relu -> g_out+g_out_h, K=256, NW=256, BN=256
// MODE 3:   out_h @ Wproj -> g_proj_h, K=256, NW=1536, BN=256
// MODE 4:   acc_h @ Wfc3 -> g_gcn, K=512, NW=256, BN=64
// ---------------------------------------------------------------------------
template <int MODE>
__global__ __launch_bounds__(256, 2) void gemm_kernel(const float* __restrict__ Af)
{
    constexpr bool A_F32 = (MODE <= 1);
    constexpr int K  = (MODE == 4) ? 512 : 256;
    constexpr int NW = (MODE <= 1) ? 512 : (MODE == 3 ? 1536 : 256);
    constexpr int BN = (MODE == 4) ? 64 : 256;
    constexpr int BM = 64, BK = 32;
    constexpr int KSTEPS = K / BK;
    constexpr int WNF = BN / 64;                 // B frags per warp
    constexpr int LDA = BK + 8;                  // 40 halves (80B rows, 16B-aligned)
    constexpr int LDB = BN + 8;
    constexpr int AS_H = BM * LDA;
    constexpr int BS_H = BK * LDB;
    constexpr int STG = AS_H + BS_H;             // halves per stage
    constexpr int NB16 = (BK * BN / 8) / 256;    // cp.async(16B) per thread for B
    constexpr int BROW = BN / 8;                 // 16B chunks per B row
    constexpr int EPIL = 32 * BN * 4;
    constexpr int SMB = (2 * STG * 2 > EPIL) ? 2 * STG * 2 : EPIL;

    __shared__ __align__(16) char smem[SMB];
    __half* As0 = reinterpret_cast<__half*>(smem);
    __half* As1 = As0 + STG;
    __half* Bs0 = As0 + AS_H;
    __half* Bs1 = As1 + AS_H;
    float*  sC  = reinterpret_cast<float*>(smem);

    const __half* Bg =
        (MODE == 0) ? g_Wedge1 : (MODE == 1) ? g_Wedge2 :
        (MODE == 2) ? g_Wweight : (MODE == 3) ? g_Wproj : g_Wfc3;
    const __half* Ah =
        (MODE == 2) ? g_text_h : (MODE == 3) ? g_out_h : g_acc_h;

    const int n0 = blockIdx.x * BN;
    const int m0 = blockIdx.y * BM;
    const int tid = threadIdx.x;
    const int wid = tid >> 5;
    const int wm = wid >> 2, wn = wid & 3;

    const unsigned sA[2] = { smem_u32(As0), smem_u32(As1) };
    const unsigned sB[2] = { smem_u32(Bs0), smem_u32(Bs1) };

    wmma::fragment<wmma::accumulator, 16, 16, 16, float> acc[2][WNF];
#pragma unroll
    for (int i = 0; i < 2; i++)
#pragma unroll
        for (int j = 0; j < WNF; j++) wmma::fill_fragment(acc[i][j], 0.0f);

    float4 raf[2];
    // per-thread fixed indices
    const int ar = tid >> 3, ac4 = (tid & 7) * 4;       // f32 A staging (2 rounds)
    const int ahr = tid >> 2, ahc = (tid & 3) * 8;      // half A cp.async

    // ---- preload stage 0 ----
    if (A_F32) {
#pragma unroll
        for (int r = 0; r < 2; r++) {
            int row = ar + r * 32;
            raf[r] = *reinterpret_cast<const float4*>(Af + (size_t)(m0 + row) * K + ac4);
        }
    } else {
        CPA16(sA[0] + (unsigned)(ahr * LDA + ahc) * 2,
              Ah + (size_t)(m0 + ahr) * K + ahc);
    }
#pragma unroll
    for (int r = 0; r < NB16; r++) {
        int idx = tid + r * 256;
        int row = idx / BROW, c = idx % BROW;
        CPA16(sB[0] + (unsigned)(row * LDB + c * 8) * 2,
              Bg + (size_t)row * NW + n0 + c * 8);
    }
    CPA_COMMIT();

    for (int ks = 0; ks < KSTEPS; ks++) {
        const int p = ks & 1;
        const __half* Asm = p ? As1 : As0;
        const __half* Bsm = p ? Bs1 : Bs0;

        if (A_F32) {   // stage p's A from regs -> smem (visible after the sync)
            __half* Aw = const_cast<__half*>(Asm);
#pragma unroll
            for (int r = 0; r < 2; r++) {
                int row = ar + r * 32;
                __half hx[4] = {__float2half_rn(raf[r].x), __float2half_rn(raf[r].y),
                                __float2half_rn(raf[r].z), __float2half_rn(raf[r].w)};
                *reinterpret_cast<uint2*>(Aw + row * LDA + ac4) =
                    *reinterpret_cast<uint2*>(hx);
            }
        }
        CPA_WAIT0();
        __syncthreads();

        if (ks + 1 < KSTEPS) {   // issue next stage (post-sync: buffer is free)
            const int k0n = (ks + 1) * BK;
            const unsigned sAn = sA[p ^ 1], sBn = sB[p ^ 1];
            if (A_F32) {
#pragma unroll
                for (int r = 0; r < 2; r++) {
                    int row = ar + r * 32;
                    raf[r] = *reinterpret_cast<const float4*>(
                        Af + (size_t)(m0 + row) * K + k0n + ac4);
                }
            } else {
                CPA16(sAn + (unsigned)(ahr * LDA + ahc) * 2,
                      Ah + (size_t)(m0 + ahr) * K + k0n + ahc);
            }
#pragma unroll
            for (int r = 0; r < NB16; r++) {
                int idx = tid + r * 256;
                int row = idx / BROW, c = idx % BROW;
                CPA16(sBn + (unsigned)(row * LDB + c * 8) * 2,
                      Bg + (size_t)(k0n + row) * NW + n0 + c * 8);
            }
            CPA_COMMIT();
        }

        // ---- mma on stage p ----
#pragma unroll
        for (int kk = 0; kk < BK; kk += 16) {
            wmma::fragment<wmma::matrix_a, 16, 16, 16, half, wmma::row_major> af[2];
            wmma::fragment<wmma::matrix_b, 16, 16, 16, half, wmma::row_major> bf[WNF];
#pragma unroll
            for (int i = 0; i < 2; i++)
                wmma::load_matrix_sync(af[i], Asm + (wm * 32 + i * 16) * LDA + kk, LDA);
#pragma unroll
            for (int j = 0; j < WNF; j++)
                wmma::load_matrix_sync(bf[j], Bsm + kk * LDB + wn * (BN / 4) + j * 16, LDB);
#pragma unroll
            for (int i = 0; i < 2; i++)
#pragma unroll
                for (int j = 0; j < WNF; j++)
                    wmma::mma_sync(acc[i][j], af[i], bf[j], acc[i][j]);
        }
    }

    // ---- epilogue: 2 passes of 32 rows via sC ----
#pragma unroll
    for (int pass = 0; pass < 2; pass++) {
        __syncthreads();
        if (wm == pass) {
#pragma unroll
            for (int i = 0; i < 2; i++)
#pragma unroll
                for (int j = 0; j < WNF; j++)
                    wmma::store_matrix_sync(&sC[(i * 16) * BN + wn * (BN / 4) + j * 16],
                                            acc[i][j], BN, wmma::mem_row_major);
        }
        __syncthreads();
        int rbase = m0 + pass * 32;
        if constexpr (MODE <= 1 || MODE == 3) {
            __half* C = (MODE == 0) ? g_e1 : (MODE == 1) ? g_e2 : g_proj_h;
#pragma unroll
            for (int r = 0; r < (32 * BN / 2) / 256; r++) {
                int idx = tid + r * 256;
                int row = idx / (BN / 2), c2 = (idx % (BN / 2)) * 2;
                __half2 hv = __floats2half2_rn(sC[row * BN + c2], sC[row * BN + c2 + 1]);
                *reinterpret_cast<__half2*>(C + (size_t)(rbase + row) * NW + n0 + c2) = hv;
            }
        } else if constexpr (MODE == 2) {
#pragma unroll
            for (int r = 0; r < 8; r++) {
                int idx = tid + r * 256;
                int row = idx >> 6, c4 = (idx & 63) * 4;
                float4 v = *reinterpret_cast<const float4*>(&sC[row * BN + c4]);
                v.x = fmaxf(v.x, 0.f); v.y = fmaxf(v.y, 0.f);
                v.z = fmaxf(v.z, 0.f); v.w = fmaxf(v.w, 0.f);
                size_t o = (size_t)(rbase + row) * 256 + c4;
                *reinterpret_cast<float4*>(g_out + o) = v;
                *reinterpret_cast<__half2*>(g_out_h + o)     = __floats2half2_rn(v.x, v.y);
                *reinterpret_cast<__half2*>(g_out_h + o + 2) = __floats2half2_rn(v.z, v.w);
            }
        } else { // MODE 4
#pragma unroll
            for (int r = 0; r < (32 * BN / 4) / 256; r++) {
                int idx = tid + r * 256;
                int row = idx / (BN / 4), c4 = (idx % (BN / 4)) * 4;
                *reinterpret_cast<float4*>(g_gcn + (size_t)(rbase + row) * 256 + n0 + c4) =
                    *reinterpret_cast<const float4*>(&sC[row * BN + c4]);
            }
        }
    }
}

// ---------------------------------------------------------------------------
// ta = text @ align_lin (fp32; precision-critical for softmax logits)
// ---------------------------------------------------------------------------
__global__ __launch_bounds__(256) void ta_kernel(const float* __restrict__ text,
                                                 const float* __restrict__ alin)
{
    __shared__ float sT[8][260];
    const int r0 = blockIdx.x * 8;
    for (int idx = threadIdx.x; idx < 8 * 64; idx += 256) {
        int r = idx >> 6, c4 = (idx & 63) * 4;
        *reinterpret_cast<float4*>(&sT[r][c4]) =
            *reinterpret_cast<const float4*>(text + (size_t)(r0 + r) * 256 + c4);
    }
    __syncthreads();
    const int n = threadIdx.x;
    float acc[8];
#pragma unroll
    for (int r = 0; r < 8; r++) acc[r] = 0.f;
    for (int k = 0; k < 256; k += 4) {
        float a0 = alin[(size_t)k * 256 + n];
        float a1 = alin[(size_t)(k + 1) * 256 + n];
        float a2 = alin[(size_t)(k + 2) * 256 + n];
        float a3 = alin[(size_t)(k + 3) * 256 + n];
#pragma unroll
        for (int r = 0; r < 8; r++) {
            float4 t = *reinterpret_cast<const float4*>(&sT[r][k]);
            acc[r] += t.x * a0 + t.y * a1 + t.z * a2 + t.w * a3;
        }
    }
#pragma unroll
    for (int r = 0; r < 8; r++)
        g_ta[(size_t)(r0 + r) * 256 + n] = acc[r];
}

// ---------------------------------------------------------------------------
// Self-alignment attention (fp32): block per (b,i)
// ---------------------------------------------------------------------------
__global__ __launch_bounds__(256) void attn_kernel(const float* __restrict__ text,
                                                   const float* __restrict__ tmask,
                                                   const float* __restrict__ align_bias,
                                                   float* __restrict__ outp)
{
    __shared__ float slog[128];
    __shared__ float s_red[2];
    const int row = blockIdx.x;
    const int b = row >> 7;
    const int tid = threadIdx.x, w = tid >> 5, lane = tid & 31;

    float ta0[8];
    {
        const float* tarow = g_ta + (size_t)row * 256 + lane * 8;
        float4 q0 = *reinterpret_cast<const float4*>(tarow);
        float4 q1 = *reinterpret_cast<const float4*>(tarow + 4);
        ta0[0] = q0.x; ta0[1] = q0.y; ta0[2] = q0.z; ta0[3] = q0.w;
        ta0[4] = q1.x; ta0[5] = q1.y; ta0[6] = q1.z; ta0[7] = q1.w;
    }
    for (int j = w; j < 128; j += 8) {
        const float* tr = text + (size_t)(b * 128 + j) * 256 + lane * 8;
        float4 t0 = *reinterpret_cast<const float4*>(tr);
        float4 t1 = *reinterpret_cast<const float4*>(tr + 4);
        float d = ta0[0] * t0.x + ta0[1] * t0.y + ta0[2] * t0.z + ta0[3] * t0.w
                + ta0[4] * t1.x + ta0[5] * t1.y + ta0[6] * t1.z + ta0[7] * t1.w;
#pragma unroll
        for (int o = 16; o > 0; o >>= 1) d += __shfl_xor_sync(0xffffffffu, d, o);
        if (lane == 0)
            slog[j] = d + (1.0f - tmask[b * 128 + j]) * -1e20f;
    }
    __syncthreads();
    if (w == 0) {
        float m = fmaxf(fmaxf(slog[lane], slog[lane + 32]),
                        fmaxf(slog[lane + 64], slog[lane + 96]));
#pragma unroll
        for (int o = 16; o > 0; o >>= 1) m = fmaxf(m, __shfl_xor_sync(0xffffffffu, m, o));
        if (lane == 0) s_red[0] = m;
    }
    __syncthreads();
    float smax = s_red[0];
    if (tid < 128) slog[tid] = expf(slog[tid] - smax);
    __syncthreads();
    if (w == 0) {
        float s = slog[lane] + slog[lane + 32] + slog[lane + 64] + slog[lane + 96];
#pragma unroll
        for (int o = 16; o > 0; o >>= 1) s += __shfl_xor_sync(0xffffffffu, s, o);
        if (lane == 0) s_red[1] = s;
    }
    __syncthreads();
    float inv = 1.0f / s_red[1];
    const int c = tid;
    float acc = 0.f;
    for (int j = 0; j < 128; j++)
        acc += slog[j] * text[(size_t)(b * 128 + j) * 256 + c];
    outp[262144 + (size_t)row * 256 + c] = acc * inv * tmask[row] + align_bias[c];
}

// ---------------------------------------------------------------------------
// Gate/accumulate: block per (b,i), warp per j (16 j's each of 8 warps).
// ---------------------------------------------------------------------------
__global__ __launch_bounds__(256) void accum_kernel(
    const float* __restrict__ adj1, const float* __restrict__ adj2,
    const float* __restrict__ w1g,  const float* __restrict__ w2g,
    const float* __restrict__ b1g,  const float* __restrict__ b2g)
{
    __shared__ float s1[8][256];
    __shared__ float s2[8][256];
    __shared__ float sadj[8][2];
    const int row = blockIdx.x;             // b*128 + i
    const int b = row >> 7;
    const int tid = threadIdx.x, w = tid >> 5, lane = tid & 31;
    const int cbase = lane * 8;

    float a1[8], a2[8], w1[8], w2[8], acc1[8], acc2[8];
    {
        const __half* ph = g_proj_h + (size_t)row * 1536;
        uint4 ua = *reinterpret_cast<const uint4*>(ph + cbase);
        uint4 ub = *reinterpret_cast<const uint4*>(ph + 512 + cbase);
        unpack8(ua, a1); unpack8(ub, a2);
    }
#pragma unroll
    for (int k = 0; k < 8; k++) {
        w1[k] = w1g[cbase + k]; w2[k] = w2g[cbase + k];
        acc1[k] = 0.f; acc2[k] = 0.f;
    }
    const float fb1 = b1g[0], fb2 = b2g[0];
    float as1 = 0.f, as2 = 0.f;

    for (int j = w; j < 128; j += 8) {
        const __half* e1p = g_e1 + ((size_t)row * 128 + j) * 512;
        const __half* e2p = g_e2 + ((size_t)row * 128 + j) * 512;
        const __half* pj  = g_proj_h + (size_t)(b * 128 + j) * 1536;
        uint4 uf1 = *reinterpret_cast<const uint4*>(e1p + cbase);
        uint4 uc1 = *reinterpret_cast<const uint4*>(e1p + 256 + cbase);
        uint4 uf2 = *reinterpret_cast<const uint4*>(e2p + cbase);
        uint4 uc2 = *reinterpret_cast<const uint4*>(e2p + 256 + cbase);
        uint4 ub1 = *reinterpret_cast<const uint4*>(pj + 256 + cbase);
        uint4 ub2 = *reinterpret_cast<const uint4*>(pj + 768 + cbase);
        uint4 uu1 = *reinterpret_cast<const uint4*>(pj + 1024 + cbase);
        uint4 uu2 = *reinterpret_cast<const uint4*>(pj + 1280 + cbase);
        float f1[8], c1[8], f2[8], c2[8], bb1[8], bb2[8], u1[8], u2[8];
        unpack8(uf1, f1); unpack8(uc1, c1);
        unpack8(uf2, f2); unpack8(uc2, c2);
        unpack8(ub1, bb1); unpack8(ub2, bb2);
        unpack8(uu1, u1);  unpack8(uu2, u2);

        float d1 = 0.f, d2 = 0.f;
#pragma unroll
        for (int k = 0; k < 8; k++) {
            d1 += w1[k] * fmaxf(a1[k] + bb1[k] + c1[k], 0.f);
            d2 += w2[k] * fmaxf(a2[k] + bb2[k] + c2[k], 0.f);
        }
#pragma unroll
        for (int o = 16; o > 0; o >>= 1) {
            d1 += __shfl_xor_sync(0xffffffffu, d1, o);
            d2 += __shfl_xor_sync(0xffffffffu, d2, o);
        }
        float av1 = adj1[(size_t)row * 128 + j];
        float av2 = adj2[(size_t)row * 128 + j];
        float g1 = av1 / (1.f + __expf(-(d1 + fb1)));
        float g2 = av2 / (1.f + __expf(-(d2 + fb2)));
        as1 += av1; as2 += av2;
#pragma unroll
        for (int k = 0; k < 8; k++) {
            acc1[k] += g1 * fmaxf(u1[k] + f1[k], 0.f);
            acc2[k] += g2 * fmaxf(u2[k] + f2[k], 0.f);
        }
    }
#pragma unroll
    for (int k = 0; k < 8; k++) {
        s1[w][cbase + k] = acc1[k];
        s2[w][cbase + k] = acc2[k];
    }
    if (lane == 0) { sadj[w][0] = as1; sadj[w][1] = as2; }
    __syncthreads();
    const int c = tid;
    float t1 = 0.f, t2 = 0.f, den1 = 1.f, den2 = 1.f;
#pragma unroll
    for (int ww = 0; ww < 8; ww++) {
        t1 += s1[ww][c]; t2 += s2[ww][c];
        den1 += sadj[ww][0]; den2 += sadj[ww][1];
    }
    g_acc_h[(size_t)row * 512 + c]       = __float2half_rn(t1 / den1);
    g_acc_h[(size_t)row * 512 + 256 + c] = __float2half_rn(t2 / den2);
}

// ---------------------------------------------------------------------------
// out = layernorm(relu(g_gcn) + out + bias); refresh g_out / g_out_h
// ---------------------------------------------------------------------------
__global__ __launch_bounds__(256) void ln_kernel(
    const float* __restrict__ bias, const float* __restrict__ gamma,
    const float* __restrict__ beta, float* __restrict__ outp, int final_it)
{
    __shared__ float s[8];
    const int row = blockIdx.x, c = threadIdx.x;
    const int w = c >> 5, lane = c & 31;
    float v = fmaxf(g_gcn[(size_t)row * 256 + c], 0.f)
            + g_out[(size_t)row * 256 + c] + bias[c];
    float t = v;
#pragma unroll
    for (int o = 16; o > 0; o >>= 1) t += __shfl_xor_sync(0xffffffffu, t, o);
    if (lane == 0) s[w] = t;
    __syncthreads();
    float m = 0.f;
#pragma unroll
    for (int i = 0; i < 8; i++) m += s[i];
    m *= (1.f / 256.f);
    __syncthreads();
    float d = v - m;
    t = d * d;
#pragma unroll
    for (int o = 16; o > 0; o >>= 1) t += __shfl_xor_sync(0xffffffffu, t, o);
    if (lane == 0) s[w] = t;
    __syncthreads();
    float var = 0.f;
#pragma unroll
    for (int i = 0; i < 8; i++) var += s[i];
    var *= (1.f / 256.f);
    float r = rsqrtf(var + 1e-5f);
    float o = d * r * gamma[c] + beta[c];
    g_out[(size_t)row * 256 + c] = o;
    g_out_h[(size_t)row * 256 + c] = __float2half_rn(o);
    if (final_it) outp[(size_t)row * 256 + c] = o;
}

// ---------------------------------------------------------------------------
extern "C" void kernel_launch(void* const* d_in, const int* in_sizes, int n_in,
                              void* d_out, int out_size)
{
    const float* text       = (const float*)d_in[0];
    const float* adj1       = (const float*)d_in[1];
    const float* adj2       = (const float*)d_in[2];
    const float* edge1      = (const float*)d_in[3];
    const float* edge2      = (const float*)d_in[4];
    const float* textmask   = (const float*)d_in[5];
    const float* weight     = (const float*)d_in[6];
    const float* bias       = (const float*)d_in[7];
    const float* gamma      = (const float*)d_in[8];
    const float* beta       = (const float*)d_in[9];
    const float* fuse1_w    = (const float*)d_in[10];
    const float* fuse2_w    = (const float*)d_in[11];
    const float* fc3_w      = (const float*)d_in[12];
    const float* fc1_w0     = (const float*)d_in[13];
    const float* fc1_w1     = (const float*)d_in[14];
    const float* fc1_b1     = (const float*)d_in[15];
    const float* fc2_w0     = (const float*)d_in[16];
    const float* fc2_w1     = (const float*)d_in[17];
    const float* fc2_b1     = (const float*)d_in[18];
    const float* align_lin  = (const float*)d_in[19];
    const float* align_bias = (const float*)d_in[20];
    float* outp = (float*)d_out;

    prep_kernel<<<1024, 256>>>(fuse1_w, fuse2_w, fc1_w0, fc2_w0, fc3_w, weight, text);

    // self-alignment path (independent)
    ta_kernel<<<128, 256>>>(text, align_lin);
    attn_kernel<<<1024, 256>>>(text, textmask, align_bias, outp);

    // edge projections
    gemm_kernel<0><<<dim3(2, 2048), 256>>>(edge1);
    gemm_kernel<1><<<dim3(2, 2048), 256>>>(edge2);

    // out = relu(text @ weight) (relu fused into epilogue)
    gemm_kernel<2><<<dim3(1, 16), 256>>>(nullptr);

    for (int it = 0; it < 3; it++) {
        gemm_kernel<3><<<dim3(6, 16), 256>>>(nullptr);
        accum_kernel<<<1024, 256>>>(adj1, adj2, fc1_w1, fc2_w1, fc1_b1, fc2_b1);
        gemm_kernel<4><<<dim3(4, 16), 256>>>(nullptr);
        ln_kernel<<<1024, 256>>>(bias, gamma, beta, outp, it == 2 ? 1 : 0);
    }
}

// round 9
// speedup vs baseline: 1.3872x; 1.0899x over previous
#include <cuda_runtime.h>
#include <cuda_fp16.h>
#include <mma.h>

using namespace nvcuda;

// Dims: B=8, N=128, D=256. BN_rows = 1024. M_edge = B*N*N = 131072.

// ---------------- static scratch (no allocations allowed) -------------------
__device__ __half g_e1[(size_t)131072 * 512];   // [m, 0:256]=e1_fuse, [256:512]=e1_fc
__device__ __half g_e2[(size_t)131072 * 512];
__device__ __half g_Wedge1[256 * 512];
__device__ __half g_Wedge2[256 * 512];
__device__ __half g_Wproj[256 * 1536];          // cols: a1|b1|a2|b2|u1|u2
__device__ __half g_Wfc3[512 * 256];
__device__ __half g_Wweight[256 * 256];
__device__ __half g_text_h[1024 * 256];
__device__ __half g_out_h[1024 * 256];
__device__ __half g_proj_h[1024 * 1536];
__device__ __half g_acc_h[1024 * 512];
__device__ float  g_out[1024 * 256];
__device__ float  g_gcn[1024 * 256];
__device__ float  g_ta[1024 * 256];

__device__ __forceinline__ unsigned smem_u32(const void* p) {
    return (unsigned)__cvta_generic_to_shared(p);
}
#define CPA16(dst, src) asm volatile("cp.async.cg.shared.global [%0], [%1], 16;" :: "r"(dst), "l"(src))
#define CPA_COMMIT() asm volatile("cp.async.commit_group;")
#define CPA_WAIT0()  asm volatile("cp.async.wait_group 0;" ::: "memory")
#define CPA_WAIT1()  asm volatile("cp.async.wait_group 1;" ::: "memory")

__device__ __forceinline__ void unpack8(uint4 v, float* f) {
    const __half2* h = reinterpret_cast<const __half2*>(&v);
#pragma unroll
    for (int e = 0; e < 4; e++) {
        float2 t = __half22float2(h[e]);
        f[2 * e] = t.x; f[2 * e + 1] = t.y;
    }
}

// ---------------------------------------------------------------------------
// prep: pack fp16 weight layouts + fp16 text
// ---------------------------------------------------------------------------
__global__ __launch_bounds__(256) void prep_kernel(
    const float* __restrict__ fuse1_w, const float* __restrict__ fuse2_w,
    const float* __restrict__ fc1_w0,  const float* __restrict__ fc2_w0,
    const float* __restrict__ fc3_w,   const float* __restrict__ weight,
    const float* __restrict__ text)
{
    const int TOTAL = 131072 + 131072 + 393216 + 131072 + 65536 + 262144;
    for (int idx = blockIdx.x * 256 + threadIdx.x; idx < TOTAL; idx += gridDim.x * 256) {
        int t = idx;
        if (t < 131072) {
            int k = t >> 9, n = t & 511;
            float v = (n < 256) ? fuse1_w[(256 + k) * 256 + n]
                                : fc1_w0[(512 + k) * 256 + (n - 256)];
            g_Wedge1[t] = __float2half_rn(v);
        } else if ((t -= 131072) < 131072) {
            int k = t >> 9, n = t & 511;
            float v = (n < 256) ? fuse2_w[(256 + k) * 256 + n]
                                : fc2_w0[(512 + k) * 256 + (n - 256)];
            g_Wedge2[t] = __float2half_rn(v);
        } else if ((t -= 131072) < 393216) {
            int k = t / 1536, n = t % 1536;
            int seg = n >> 8, c = n & 255;
            float v;
            switch (seg) {
                case 0:  v = fc1_w0[k * 256 + c]; break;
                case 1:  v = fc1_w0[(256 + k) * 256 + c]; break;
                case 2:  v = fc2_w0[k * 256 + c]; break;
                case 3:  v = fc2_w0[(256 + k) * 256 + c]; break;
                case 4:  v = fuse1_w[k * 256 + c]; break;
                default: v = fuse2_w[k * 256 + c]; break;
            }
            g_Wproj[t] = __float2half_rn(v);
        } else if ((t -= 393216) < 131072) {
            g_Wfc3[t] = __float2half_rn(fc3_w[t]);
        } else if ((t -= 131072) < 65536) {
            g_Wweight[t] = __float2half_rn(weight[t]);
        } else {
            t -= 65536;
            g_text_h[t] = __float2half_rn(text[t]);
        }
    }
}

// ---------------------------------------------------------------------------
// 3-stage cp.async wmma GEMM: C[M,N] = A[M,K] @ B[K,N] (row-major).
// Per step ks: wait_group(1) [oldest stage landed] -> sync -> issue stage
// ks+2 -> mma(ks) -> [f32-A: STS A(ks+1), LDG A(ks+2)].
// Buffer (ks+2)%3 was last read at mma(ks-1), complete for all warps before
// this step's sync -> race-free. Dynamic smem (66KB > 48KB static limit).
// __launch_bounds__(256,2) keeps regs <=128 (R7: 136 regs -> occ collapse).
// ---------------------------------------------------------------------------
template <int MODE>
__global__ __launch_bounds__(256, 2) void gemm_kernel(const float* __restrict__ Af)
{
    constexpr bool A_F32 = (MODE <= 1);
    constexpr int K  = (MODE == 4) ? 512 : 256;
    constexpr int NW = (MODE <= 1) ? 512 : (MODE == 3 ? 1536 : 256);
    constexpr int BN = (MODE == 4) ? 64 : 256;
    constexpr int BM = 64, BK = 32;
    constexpr int KSTEPS = K / BK;
    constexpr int WNF = BN / 64;                 // B frags per warp
    constexpr int LDA = BK + 8;
    constexpr int LDB = BN + 8;
    constexpr int AS_H = BM * LDA;               // halves
    constexpr int BS_H = BK * LDB;
    constexpr int STGB = (AS_H + BS_H) * 2;      // bytes per stage
    constexpr int NB16 = (BK * BN / 8) / 256;    // cp.async(16B)/thread for B
    constexpr int BROW = BN / 8;

    extern __shared__ __align__(16) char smem[];
    float* sC = reinterpret_cast<float*>(smem);
    const unsigned sbase = smem_u32(smem);

    const __half* Bg =
        (MODE == 0) ? g_Wedge1 : (MODE == 1) ? g_Wedge2 :
        (MODE == 2) ? g_Wweight : (MODE == 3) ? g_Wproj : g_Wfc3;
    const __half* Ah =
        (MODE == 2) ? g_text_h : (MODE == 3) ? g_out_h : g_acc_h;

    const int n0 = blockIdx.x * BN;
    const int m0 = blockIdx.y * BM;
    const int tid = threadIdx.x;
    const int wid = tid >> 5;
    const int wm = wid >> 2, wn = wid & 3;

    wmma::fragment<wmma::accumulator, 16, 16, 16, float> acc[2][WNF];
#pragma unroll
    for (int i = 0; i < 2; i++)
#pragma unroll
        for (int j = 0; j < WNF; j++) wmma::fill_fragment(acc[i][j], 0.0f);

    float4 raf[2];
    const int ar = tid >> 3, ac4 = (tid & 7) * 4;    // f32 A staging
    const int ahr = tid >> 2, ahc = (tid & 3) * 8;   // half A cp.async
    const unsigned aoff = (unsigned)(ahr * LDA + ahc) * 2;

    // ---- prologue: stage 0 (and stage 1 loads) ----
    if (A_F32) {
#pragma unroll
        for (int r = 0; r < 2; r++) {
            int row = ar + r * 32;
            raf[r] = *reinterpret_cast<const float4*>(Af + (size_t)(m0 + row) * K + ac4);
        }
        __half* A0 = reinterpret_cast<__half*>(smem);
#pragma unroll
        for (int r = 0; r < 2; r++) {
            int row = ar + r * 32;
            __half hx[4] = {__float2half_rn(raf[r].x), __float2half_rn(raf[r].y),
                            __float2half_rn(raf[r].z), __float2half_rn(raf[r].w)};
            *reinterpret_cast<uint2*>(A0 + row * LDA + ac4) = *reinterpret_cast<uint2*>(hx);
        }
    } else {
        CPA16(sbase + aoff, Ah + (size_t)(m0 + ahr) * K + ahc);
    }
#pragma unroll
    for (int r = 0; r < NB16; r++) {
        int idx = tid + r * 256;
        int row = idx / BROW, c = idx % BROW;
        CPA16(sbase + (unsigned)(AS_H + row * LDB + c * 8) * 2,
              Bg + (size_t)row * NW + n0 + c * 8);
    }
    CPA_COMMIT();

    if (KSTEPS > 1) {   // stage 1
        const unsigned s1 = sbase + STGB;
        if (A_F32) {
#pragma unroll
            for (int r = 0; r < 2; r++) {
                int row = ar + r * 32;
                raf[r] = *reinterpret_cast<const float4*>(
                    Af + (size_t)(m0 + row) * K + BK + ac4);
            }
        } else {
            CPA16(s1 + aoff, Ah + (size_t)(m0 + ahr) * K + BK + ahc);
        }
#pragma unroll
        for (int r = 0; r < NB16; r++) {
            int idx = tid + r * 256;
            int row = idx / BROW, c = idx % BROW;
            CPA16(s1 + (unsigned)(AS_H + row * LDB + c * 8) * 2,
                  Bg + (size_t)(BK + row) * NW + n0 + c * 8);
        }
        CPA_COMMIT();
    }

    for (int ks = 0; ks < KSTEPS; ks++) {
        if (ks + 1 < KSTEPS) { CPA_WAIT1(); } else { CPA_WAIT0(); }
        __syncthreads();

        if (ks + 2 < KSTEPS) {   // issue stage ks+2 (buffer read finished at mma(ks-1))
            const int k0n = (ks + 2) * BK;
            const unsigned sn = sbase + ((ks + 2) % 3) * STGB;
            if (!A_F32) {
                CPA16(sn + aoff, Ah + (size_t)(m0 + ahr) * K + k0n + ahc);
            }
#pragma unroll
            for (int r = 0; r < NB16; r++) {
                int idx = tid + r * 256;
                int row = idx / BROW, c = idx % BROW;
                CPA16(sn + (unsigned)(AS_H + row * LDB + c * 8) * 2,
                      Bg + (size_t)(k0n + row) * NW + n0 + c * 8);
            }
            CPA_COMMIT();
        }

        // ---- mma on stage ks%3 ----
        const __half* Asm = reinterpret_cast<const __half*>(smem + (ks % 3) * STGB);
        const __half* Bsm = Asm + AS_H;
#pragma unroll
        for (int kk = 0; kk < BK; kk += 16) {
            wmma::fragment<wmma::matrix_a, 16, 16, 16, half, wmma::row_major> af[2];
            wmma::fragment<wmma::matrix_b, 16, 16, 16, half, wmma::row_major> bf[WNF];
#pragma unroll
            for (int i = 0; i < 2; i++)
                wmma::load_matrix_sync(af[i], Asm + (wm * 32 + i * 16) * LDA + kk, LDA);
#pragma unroll
            for (int j = 0; j < WNF; j++)
                wmma::load_matrix_sync(bf[j], Bsm + kk * LDB + wn * (BN / 4) + j * 16, LDB);
#pragma unroll
            for (int i = 0; i < 2; i++)
#pragma unroll
                for (int j = 0; j < WNF; j++)
                    wmma::mma_sync(acc[i][j], af[i], bf[j], acc[i][j]);
        }

        if (A_F32) {
            if (ks + 1 < KSTEPS) {   // STS A(ks+1); visible after next step's sync
                __half* An = reinterpret_cast<__half*>(smem + ((ks + 1) % 3) * STGB);
#pragma unroll
                for (int r = 0; r < 2; r++) {
                    int row = ar + r * 32;
                    __half hx[4] = {__float2half_rn(raf[r].x), __float2half_rn(raf[r].y),
                                    __float2half_rn(raf[r].z), __float2half_rn(raf[r].w)};
                    *reinterpret_cast<uint2*>(An + row * LDA + ac4) =
                        *reinterpret_cast<uint2*>(hx);
                }
            }
            if (ks + 2 < KSTEPS) {   // LDG A(ks+2)
                const int k0n = (ks + 2) * BK;
#pragma unroll
                for (int r = 0; r < 2; r++) {
                    int row = ar + r * 32;
                    raf[r] = *reinterpret_cast<const float4*>(
                        Af + (size_t)(m0 + row) * K + k0n + ac4);
                }
            }
        }
    }

    // ---- epilogue: 2 passes of 32 rows via sC (aliases stage smem) ----
#pragma unroll
    for (int pass = 0; pass < 2; pass++) {
        __syncthreads();
        if (wm == pass) {
#pragma unroll
            for (int i = 0; i < 2; i++)
#pragma unroll
                for (int j = 0; j < WNF; j++)
                    wmma::store_matrix_sync(&sC[(i * 16) * BN + wn * (BN / 4) + j * 16],
                                            acc[i][j], BN, wmma::mem_row_major);
        }
        __syncthreads();
        int rbase = m0 + pass * 32;
        if constexpr (MODE <= 1 || MODE == 3) {
            __half* C = (MODE == 0) ? g_e1 : (MODE == 1) ? g_e2 : g_proj_h;
#pragma unroll
            for (int r = 0; r < (32 * BN / 2) / 256; r++) {
                int idx = tid + r * 256;
                int row = idx / (BN / 2), c2 = (idx % (BN / 2)) * 2;
                __half2 hv = __floats2half2_rn(sC[row * BN + c2], sC[row * BN + c2 + 1]);
                *reinterpret_cast<__half2*>(C + (size_t)(rbase + row) * NW + n0 + c2) = hv;
            }
        } else if constexpr (MODE == 2) {
#pragma unroll
            for (int r = 0; r < 8; r++) {
                int idx = tid + r * 256;
                int row = idx >> 6, c4 = (idx & 63) * 4;
                float4 v = *reinterpret_cast<const float4*>(&sC[row * BN + c4]);
                v.x = fmaxf(v.x, 0.f); v.y = fmaxf(v.y, 0.f);
                v.z = fmaxf(v.z, 0.f); v.w = fmaxf(v.w, 0.f);
                size_t o = (size_t)(rbase + row) * 256 + c4;
                *reinterpret_cast<float4*>(g_out + o) = v;
                *reinterpret_cast<__half2*>(g_out_h + o)     = __floats2half2_rn(v.x, v.y);
                *reinterpret_cast<__half2*>(g_out_h + o + 2) = __floats2half2_rn(v.z, v.w);
            }
        } else { // MODE 4
#pragma unroll
            for (int r = 0; r < (32 * BN / 4) / 256; r++) {
                int idx = tid + r * 256;
                int row = idx / (BN / 4), c4 = (idx % (BN / 4)) * 4;
                *reinterpret_cast<float4*>(g_gcn + (size_t)(rbase + row) * 256 + n0 + c4) =
                    *reinterpret_cast<const float4*>(&sC[row * BN + c4]);
            }
        }
    }
}

// host-side smem size per mode (mirrors kernel constants)
static inline int gemm_smem_bytes(int BN) {
    int stgb = (64 * 40 + 32 * (BN + 8)) * 2;
    int pipe = 3 * stgb;
    int epil = 32 * BN * 4;
    return pipe > epil ? pipe : epil;
}

// ---------------------------------------------------------------------------
// ta = text @ align_lin (fp32; precision-critical for softmax logits)
// ---------------------------------------------------------------------------
__global__ __launch_bounds__(256) void ta_kernel(const float* __restrict__ text,
                                                 const float* __restrict__ alin)
{
    __shared__ float sT[8][260];
    const int r0 = blockIdx.x * 8;
    for (int idx = threadIdx.x; idx < 8 * 64; idx += 256) {
        int r = idx >> 6, c4 = (idx & 63) * 4;
        *reinterpret_cast<float4*>(&sT[r][c4]) =
            *reinterpret_cast<const float4*>(text + (size_t)(r0 + r) * 256 + c4);
    }
    __syncthreads();
    const int n = threadIdx.x;
    float acc[8];
#pragma unroll
    for (int r = 0; r < 8; r++) acc[r] = 0.f;
    for (int k = 0; k < 256; k += 4) {
        float a0 = alin[(size_t)k * 256 + n];
        float a1 = alin[(size_t)(k + 1) * 256 + n];
        float a2 = alin[(size_t)(k + 2) * 256 + n];
        float a3 = alin[(size_t)(k + 3) * 256 + n];
#pragma unroll
        for (int r = 0; r < 8; r++) {
            float4 t = *reinterpret_cast<const float4*>(&sT[r][k]);
            acc[r] += t.x * a0 + t.y * a1 + t.z * a2 + t.w * a3;
        }
    }
#pragma unroll
    for (int r = 0; r < 8; r++)
        g_ta[(size_t)(r0 + r) * 256 + n] = acc[r];
}

// ---------------------------------------------------------------------------
// Self-alignment attention (fp32): block per (b,i)
// ---------------------------------------------------------------------------
__global__ __launch_bounds__(256) void attn_kernel(const float* __restrict__ text,
                                                   const float* __restrict__ tmask,
                                                   const float* __restrict__ align_bias,
                                                   float* __restrict__ outp)
{
    __shared__ float slog[128];
    __shared__ float s_red[2];
    const int row = blockIdx.x;
    const int b = row >> 7;
    const int tid = threadIdx.x, w = tid >> 5, lane = tid & 31;

    float ta0[8];
    {
        const float* tarow = g_ta + (size_t)row * 256 + lane * 8;
        float4 q0 = *reinterpret_cast<const float4*>(tarow);
        float4 q1 = *reinterpret_cast<const float4*>(tarow + 4);
        ta0[0] = q0.x; ta0[1] = q0.y; ta0[2] = q0.z; ta0[3] = q0.w;
        ta0[4] = q1.x; ta0[5] = q1.y; ta0[6] = q1.z; ta0[7] = q1.w;
    }
    for (int j = w; j < 128; j += 8) {
        const float* tr = text + (size_t)(b * 128 + j) * 256 + lane * 8;
        float4 t0 = *reinterpret_cast<const float4*>(tr);
        float4 t1 = *reinterpret_cast<const float4*>(tr + 4);
        float d = ta0[0] * t0.x + ta0[1] * t0.y + ta0[2] * t0.z + ta0[3] * t0.w
                + ta0[4] * t1.x + ta0[5] * t1.y + ta0[6] * t1.z + ta0[7] * t1.w;
#pragma unroll
        for (int o = 16; o > 0; o >>= 1) d += __shfl_xor_sync(0xffffffffu, d, o);
        if (lane == 0)
            slog[j] = d + (1.0f - tmask[b * 128 + j]) * -1e20f;
    }
    __syncthreads();
    if (w == 0) {
        float m = fmaxf(fmaxf(slog[lane], slog[lane + 32]),
                        fmaxf(slog[lane + 64], slog[lane + 96]));
#pragma unroll
        for (int o = 16; o > 0; o >>= 1) m = fmaxf(m, __shfl_xor_sync(0xffffffffu, m, o));
        if (lane == 0) s_red[0] = m;
    }
    __syncthreads();
    float smax = s_red[0];
    if (tid < 128) slog[tid] = expf(slog[tid] - smax);
    __syncthreads();
    if (w == 0) {
        float s = slog[lane] + slog[lane + 32] + slog[lane + 64] + slog[lane + 96];
#pragma unroll
        for (int o = 16; o > 0; o >>= 1) s += __shfl_xor_sync(0xffffffffu, s, o);
        if (lane == 0) s_red[1] = s;
    }
    __syncthreads();
    float inv = 1.0f / s_red[1];
    const int c = tid;
    float acc = 0.f;
    for (int j = 0; j < 128; j++)
        acc += slog[j] * text[(size_t)(b * 128 + j) * 256 + c];
    outp[262144 + (size_t)row * 256 + c] = acc * inv * tmask[row] + align_bias[c];
}

// ---------------------------------------------------------------------------
// Gate/accumulate: block per (b,i), warp per j (16 j's each of 8 warps).
// ---------------------------------------------------------------------------
__global__ __launch_bounds__(256) void accum_kernel(
    const float* __restrict__ adj1, const float* __restrict__ adj2,
    const float* __restrict__ w1g,  const float* __restrict__ w2g,
    const float* __restrict__ b1g,  const float* __restrict__ b2g)
{
    __shared__ float s1[8][256];
    __shared__ float s2[8][256];
    __shared__ float sadj[8][2];
    const int row = blockIdx.x;             // b*128 + i
    const int b = row >> 7;
    const int tid = threadIdx.x, w = tid >> 5, lane = tid & 31;
    const int cbase = lane * 8;

    float a1[8], a2[8], w1[8], w2[8], acc1[8], acc2[8];
    {
        const __half* ph = g_proj_h + (size_t)row * 1536;
        uint4 ua = *reinterpret_cast<const uint4*>(ph + cbase);
        uint4 ub = *reinterpret_cast<const uint4*>(ph + 512 + cbase);
        unpack8(ua, a1); unpack8(ub, a2);
    }
#pragma unroll
    for (int k = 0; k < 8; k++) {
        w1[k] = w1g[cbase + k]; w2[k] = w2g[cbase + k];
        acc1[k] = 0.f; acc2[k] = 0.f;
    }
    const float fb1 = b1g[0], fb2 = b2g[0];
    float as1 = 0.f, as2 = 0.f;

    for (int j = w; j < 128; j += 8) {
        const __half* e1p = g_e1 + ((size_t)row * 128 + j) * 512;
        const __half* e2p = g_e2 + ((size_t)row * 128 + j) * 512;
        const __half* pj  = g_proj_h + (size_t)(b * 128 + j) * 1536;
        uint4 uf1 = *reinterpret_cast<const uint4*>(e1p + cbase);
        uint4 uc1 = *reinterpret_cast<const uint4*>(e1p + 256 + cbase);
        uint4 uf2 = *reinterpret_cast<const uint4*>(e2p + cbase);
        uint4 uc2 = *reinterpret_cast<const uint4*>(e2p + 256 + cbase);
        uint4 ub1 = *reinterpret_cast<const uint4*>(pj + 256 + cbase);
        uint4 ub2 = *reinterpret_cast<const uint4*>(pj + 768 + cbase);
        uint4 uu1 = *reinterpret_cast<const uint4*>(pj + 1024 + cbase);
        uint4 uu2 = *reinterpret_cast<const uint4*>(pj + 1280 + cbase);
        float f1[8], c1[8], f2[8], c2[8], bb1[8], bb2[8], u1[8], u2[8];
        unpack8(uf1, f1); unpack8(uc1, c1);
        unpack8(uf2, f2); unpack8(uc2, c2);
        unpack8(ub1, bb1); unpack8(ub2, bb2);
        unpack8(uu1, u1);  unpack8(uu2, u2);

        float d1 = 0.f, d2 = 0.f;
#pragma unroll
        for (int k = 0; k < 8; k++) {
            d1 += w1[k] * fmaxf(a1[k] + bb1[k] + c1[k], 0.f);
            d2 += w2[k] * fmaxf(a2[k] + bb2[k] + c2[k], 0.f);
        }
#pragma unroll
        for (int o = 16; o > 0; o >>= 1) {
            d1 += __shfl_xor_sync(0xffffffffu, d1, o);
            d2 += __shfl_xor_sync(0xffffffffu, d2, o);
        }
        float av1 = adj1[(size_t)row * 128 + j];
        float av2 = adj2[(size_t)row * 128 + j];
        float g1 = av1 / (1.f + __expf(-(d1 + fb1)));
        float g2 = av2 / (1.f + __expf(-(d2 + fb2)));
        as1 += av1; as2 += av2;
#pragma unroll
        for (int k = 0; k < 8; k++) {
            acc1[k] += g1 * fmaxf(u1[k] + f1[k], 0.f);
            acc2[k] += g2 * fmaxf(u2[k] + f2[k], 0.f);
        }
    }
#pragma unroll
    for (int k = 0; k < 8; k++) {
        s1[w][cbase + k] = acc1[k];
        s2[w][cbase + k] = acc2[k];
    }
    if (lane == 0) { sadj[w][0] = as1; sadj[w][1] = as2; }
    __syncthreads();
    const int c = tid;
    float t1 = 0.f, t2 = 0.f, den1 = 1.f, den2 = 1.f;
#pragma unroll
    for (int ww = 0; ww < 8; ww++) {
        t1 += s1[ww][c]; t2 += s2[ww][c];
        den1 += sadj[ww][0]; den2 += sadj[ww][1];
    }
    g_acc_h[(size_t)row * 512 + c]       = __float2half_rn(t1 / den1);
    g_acc_h[(size_t)row * 512 + 256 + c] = __float2half_rn(t2 / den2);
}

// ---------------------------------------------------------------------------
// out = layernorm(relu(g_gcn) + out + bias); refresh g_out / g_out_h
// ---------------------------------------------------------------------------
__global__ __launch_bounds__(256) void ln_kernel(
    const float* __restrict__ bias, const float* __restrict__ gamma,
    const float* __restrict__ beta, float* __restrict__ outp, int final_it)
{
    __shared__ float s[8];
    const int row = blockIdx.x, c = threadIdx.x;
    const int w = c >> 5, lane = c & 31;
    float v = fmaxf(g_gcn[(size_t)row * 256 + c], 0.f)
            + g_out[(size_t)row * 256 + c] + bias[c];
    float t = v;
#pragma unroll
    for (int o = 16; o > 0; o >>= 1) t += __shfl_xor_sync(0xffffffffu, t, o);
    if (lane == 0) s[w] = t;
    __syncthreads();
    float m = 0.f;
#pragma unroll
    for (int i = 0; i < 8; i++) m += s[i];
    m *= (1.f / 256.f);
    __syncthreads();
    float d = v - m;
    t = d * d;
#pragma unroll
    for (int o = 16; o > 0; o >>= 1) t += __shfl_xor_sync(0xffffffffu, t, o);
    if (lane == 0) s[w] = t;
    __syncthreads();
    float var = 0.f;
#pragma unroll
    for (int i = 0; i < 8; i++) var += s[i];
    var *= (1.f / 256.f);
    float r = rsqrtf(var + 1e-5f);
    float o = d * r * gamma[c] + beta[c];
    g_out[(size_t)row * 256 + c] = o;
    g_out_h[(size_t)row * 256 + c] = __float2half_rn(o);
    if (final_it) outp[(size_t)row * 256 + c] = o;
}

// ---------------------------------------------------------------------------
extern "C" void kernel_launch(void* const* d_in, const int* in_sizes, int n_in,
                              void* d_out, int out_size)
{
    const float* text       = (const float*)d_in[0];
    const float* adj1       = (const float*)d_in[1];
    const float* adj2       = (const float*)d_in[2];
    const float* edge1      = (const float*)d_in[3];
    const float* edge2      = (const float*)d_in[4];
    const float* textmask   = (const float*)d_in[5];
    const float* weight     = (const float*)d_in[6];
    const float* bias       = (const float*)d_in[7];
    const float* gamma      = (const float*)d_in[8];
    const float* beta       = (const float*)d_in[9];
    const float* fuse1_w    = (const float*)d_in[10];
    const float* fuse2_w    = (const float*)d_in[11];
    const float* fc3_w      = (const float*)d_in[12];
    const float* fc1_w0     = (const float*)d_in[13];
    const float* fc1_w1     = (const float*)d_in[14];
    const float* fc1_b1     = (const float*)d_in[15];
    const float* fc2_w0     = (const float*)d_in[16];
    const float* fc2_w1     = (const float*)d_in[17];
    const float* fc2_b1     = (const float*)d_in[18];
    const float* align_lin  = (const float*)d_in[19];
    const float* align_bias = (const float*)d_in[20];
    float* outp = (float*)d_out;

    const int smb256 = gemm_smem_bytes(256);   // 66048
    const int smb64  = gemm_smem_bytes(64);    // 29184
    cudaFuncSetAttribute(gemm_kernel<0>, cudaFuncAttributeMaxDynamicSharedMemorySize, smb256);
    cudaFuncSetAttribute(gemm_kernel<1>, cudaFuncAttributeMaxDynamicSharedMemorySize, smb256);
    cudaFuncSetAttribute(gemm_kernel<2>, cudaFuncAttributeMaxDynamicSharedMemorySize, smb256);
    cudaFuncSetAttribute(gemm_kernel<3>, cudaFuncAttributeMaxDynamicSharedMemorySize, smb256);
    cudaFuncSetAttribute(gemm_kernel<4>, cudaFuncAttributeMaxDynamicSharedMemorySize, smb64);

    prep_kernel<<<1024, 256>>>(fuse1_w, fuse2_w, fc1_w0, fc2_w0, fc3_w, weight, text);

    // self-alignment path (independent)
    ta_kernel<<<128, 256>>>(text, align_lin);
    attn_kernel<<<1024, 256>>>(text, textmask, align_bias, outp);

    // edge projections
    gemm_kernel<0><<<dim3(2, 2048), 256, smb256>>>(edge1);
    gemm_kernel<1><<<dim3(2, 2048), 256, smb256>>>(edge2);

    // out = relu(text @ weight) (relu fused into epilogue)
    gemm_kernel<2><<<dim3(1, 16), 256, smb256>>>(nullptr);

    for (int it = 0; it < 3; it++) {
        gemm_kernel<3><<<dim3(6, 16), 256, smb256>>>(nullptr);
        accum_kernel<<<1024, 256>>>(adj1, adj2, fc1_w1, fc2_w1, fc1_b1, fc2_b1);
        gemm_kernel<4><<<dim3(4, 16), 256, smb64>>>(nullptr);
        ln_kernel<<<1024, 256>>>(bias, gamma, beta, outp, it == 2 ? 1 : 0);
    }
}

// round 16
// speedup vs baseline: 1.4283x; 1.0296x over previous
#include <cuda_runtime.h>
#include <cuda_fp16.h>
#include <cstdint>
#include <cstddef>
#include <mma.h>

using namespace nvcuda;

// Dims: B=8, N=128, D=256. BN_rows = 1024. M_edge = B*N*N = 131072.
// NOTE (R14): harness compiles via compute_103 PTX (no 'a') -> tcgen05/TMEM
// unavailable. wmma/HMMA + cp.async is the tensor path ceiling here.

// ---------------- static scratch (no allocations allowed) -------------------
__device__ __half g_e1[(size_t)131072 * 512];   // [m, 0:256]=e1_fuse, [256:512]=e1_fc
__device__ __half g_e2[(size_t)131072 * 512];
__device__ __half g_Wedge1[256 * 512];          // [k, n] row-major
__device__ __half g_Wedge2[256 * 512];
__device__ __half g_Wproj[256 * 1536];          // cols: a1|b1|a2|b2|u1|u2
__device__ __half g_Wfc3[512 * 256];
__device__ __half g_Wweight[256 * 256];
__device__ __half g_text_h[1024 * 256];
__device__ __half g_out_h[1024 * 256];
__device__ __half g_proj_h[1024 * 1536];
__device__ __half g_acc_h[1024 * 512];
__device__ float  g_out[1024 * 256];
__device__ float  g_gcn[1024 * 256];
__device__ float  g_ta[1024 * 256];

__device__ __forceinline__ unsigned smem_u32(const void* p) {
    return (unsigned)__cvta_generic_to_shared(p);
}
#define CPA16(dst, src) asm volatile("cp.async.cg.shared.global [%0], [%1], 16;" :: "r"(dst), "l"(src))
#define CPA_COMMIT() asm volatile("cp.async.commit_group;")
#define CPA_WAIT0()  asm volatile("cp.async.wait_group 0;" ::: "memory")
#define CPA_WAIT1()  asm volatile("cp.async.wait_group 1;" ::: "memory")
#define CPA_WAIT2()  asm volatile("cp.async.wait_group 2;" ::: "memory")

__device__ __forceinline__ void unpack8(uint4 v, float* f) {
    const __half2* h = reinterpret_cast<const __half2*>(&v);
#pragma unroll
    for (int e = 0; e < 4; e++) {
        float2 t = __half22float2(h[e]);
        f[2 * e] = t.x; f[2 * e + 1] = t.y;
    }
}

// ---------------------------------------------------------------------------
// prep: pack fp16 weight layouts + fp16 text
// ---------------------------------------------------------------------------
__global__ __launch_bounds__(256) void prep_kernel(
    const float* __restrict__ fuse1_w, const float* __restrict__ fuse2_w,
    const float* __restrict__ fc1_w0,  const float* __restrict__ fc2_w0,
    const float* __restrict__ fc3_w,   const float* __restrict__ weight,
    const float* __restrict__ text)
{
    const int TOTAL = 131072 + 131072 + 393216 + 131072 + 65536 + 262144;
    for (int idx = blockIdx.x * 256 + threadIdx.x; idx < TOTAL; idx += gridDim.x * 256) {
        int t = idx;
        if (t < 131072) {
            int k = t >> 9, n = t & 511;
            float v = (n < 256) ? fuse1_w[(256 + k) * 256 + n]
                                : fc1_w0[(512 + k) * 256 + (n - 256)];
            g_Wedge1[t] = __float2half_rn(v);
        } else if ((t -= 131072) < 131072) {
            int k = t >> 9, n = t & 511;
            float v = (n < 256) ? fuse2_w[(256 + k) * 256 + n]
                                : fc2_w0[(512 + k) * 256 + (n - 256)];
            g_Wedge2[t] = __float2half_rn(v);
        } else if ((t -= 131072) < 393216) {
            int k = t / 1536, n = t % 1536;
            int seg = n >> 8, c = n & 255;
            float v;
            switch (seg) {
                case 0:  v = fc1_w0[k * 256 + c]; break;
                case 1:  v = fc1_w0[(256 + k) * 256 + c]; break;
                case 2:  v = fc2_w0[k * 256 + c]; break;
                case 3:  v = fc2_w0[(256 + k) * 256 + c]; break;
                case 4:  v = fuse1_w[k * 256 + c]; break;
                default: v = fuse2_w[k * 256 + c]; break;
            }
            g_Wproj[t] = __float2half_rn(v);
        } else if ((t -= 393216) < 131072) {
            g_Wfc3[t] = __float2half_rn(fc3_w[t]);
        } else if ((t -= 131072) < 65536) {
            g_Wweight[t] = __float2half_rn(weight[t]);
        } else {
            t -= 65536;
            g_text_h[t] = __float2half_rn(text[t]);
        }
    }
}

// ---------------------------------------------------------------------------
// 4-stage cp.async wmma GEMM: C[M,N] = A[M,K] @ B[K,N] (row-major).
// Per step ks: wait(pending) -> sync -> issue B stage ks+3 -> mma(ks) ->
// [f32-A: STS A(ks+1), LDG A(ks+2)].  Tail: wait2 / wait1 / wait0.
// Buffer (ks+3)%4 last read at mma(ks-1) (pre-sync) -> race-free.
// __launch_bounds__(256,2) keeps regs <=128 (R7: occupancy collapse at 136).
// MODE 0/1: edge1/edge2 (A fp32 ext), K=256, NW=512, BN=256
// MODE 2:   text_h @ Wweight -> relu -> g_out+g_out_h, K=256, NW=256, BN=256
// MODE 3:   out_h @ Wproj -> g_proj_h, K=256, NW=1536, BN=256
// MODE 4:   acc_h @ Wfc3 -> g_gcn, K=512, NW=256, BN=64
// ---------------------------------------------------------------------------
template <int MODE>
__global__ __launch_bounds__(256, 2) void gemm_kernel(const float* __restrict__ Af)
{
    constexpr bool A_F32 = (MODE <= 1);
    constexpr int K  = (MODE == 4) ? 512 : 256;
    constexpr int NW = (MODE <= 1) ? 512 : (MODE == 3 ? 1536 : 256);
    constexpr int BN = (MODE == 4) ? 64 : 256;
    constexpr int BM = 64, BK = 32;
    constexpr int KSTEPS = K / BK;
    constexpr int WNF = BN / 64;
    constexpr int LDA = BK + 8;
    constexpr int LDB = BN + 8;
    constexpr int AS_H = BM * LDA;
    constexpr int BS_H = BK * LDB;
    constexpr int STGB = (AS_H + BS_H) * 2;      // bytes per stage
    constexpr int NB16 = (BK * BN / 8) / 256;
    constexpr int BROW = BN / 8;

    extern __shared__ __align__(16) char smem[];
    float* sC = reinterpret_cast<float*>(smem);
    const unsigned sbase = smem_u32(smem);

    const __half* Bg =
        (MODE == 0) ? g_Wedge1 : (MODE == 1) ? g_Wedge2 :
        (MODE == 2) ? g_Wweight : (MODE == 3) ? g_Wproj : g_Wfc3;
    const __half* Ah =
        (MODE == 2) ? g_text_h : (MODE == 3) ? g_out_h : g_acc_h;

    const int n0 = blockIdx.x * BN;
    const int m0 = blockIdx.y * BM;
    const int tid = threadIdx.x;
    const int wid = tid >> 5;
    const int wm = wid >> 2, wn = wid & 3;

    wmma::fragment<wmma::accumulator, 16, 16, 16, float> acc[2][WNF];
#pragma unroll
    for (int i = 0; i < 2; i++)
#pragma unroll
        for (int j = 0; j < WNF; j++) wmma::fill_fragment(acc[i][j], 0.0f);

    float4 raf[2];
    const int ar = tid >> 3, ac4 = (tid & 7) * 4;    // f32 A staging
    const int ahr = tid >> 2, ahc = (tid & 3) * 8;   // half A cp.async
    const unsigned aoff = (unsigned)(ahr * LDA + ahc) * 2;

    auto issueB = [&](int ksn) {
        const int k0n = ksn * BK;
        const unsigned sn = sbase + (ksn % 4) * STGB;
        if (!A_F32)
            CPA16(sn + aoff, Ah + (size_t)(m0 + ahr) * K + k0n + ahc);
#pragma unroll
        for (int r = 0; r < NB16; r++) {
            int idx = tid + r * 256;
            int row = idx / BROW, c = idx % BROW;
            CPA16(sn + (unsigned)(AS_H + row * LDB + c * 8) * 2,
                  Bg + (size_t)(k0n + row) * NW + n0 + c * 8);
        }
        CPA_COMMIT();
    };

    // ---- prologue: B stages 0,1,2; A stage0 STS'd, stage1 in regs ----
    if (A_F32) {
        __half* A0 = reinterpret_cast<__half*>(smem);
#pragma unroll
        for (int r = 0; r < 2; r++) {
            int row = ar + r * 32;
            float4 v = *reinterpret_cast<const float4*>(Af + (size_t)(m0 + row) * K + ac4);
            __half hx[4] = {__float2half_rn(v.x), __float2half_rn(v.y),
                            __float2half_rn(v.z), __float2half_rn(v.w)};
            *reinterpret_cast<uint2*>(A0 + row * LDA + ac4) = *reinterpret_cast<uint2*>(hx);
        }
#pragma unroll
        for (int r = 0; r < 2; r++) {
            int row = ar + r * 32;
            raf[r] = *reinterpret_cast<const float4*>(
                Af + (size_t)(m0 + row) * K + BK + ac4);
        }
    }
    issueB(0);
    if (KSTEPS > 1) issueB(1);
    if (KSTEPS > 2) issueB(2);

    for (int ks = 0; ks < KSTEPS; ks++) {
        if (ks + 2 < KSTEPS)      { CPA_WAIT2(); }
        else if (ks + 1 < KSTEPS) { CPA_WAIT1(); }
        else                      { CPA_WAIT0(); }
        __syncthreads();

        if (ks + 3 < KSTEPS) issueB(ks + 3);

        // ---- mma on stage ks%4 ----
        const __half* Asm = reinterpret_cast<const __half*>(smem + (ks % 4) * STGB);
        const __half* Bsm = Asm + AS_H;
#pragma unroll
        for (int kk = 0; kk < BK; kk += 16) {
            wmma::fragment<wmma::matrix_a, 16, 16, 16, half, wmma::row_major> af[2];
            wmma::fragment<wmma::matrix_b, 16, 16, 16, half, wmma::row_major> bf[WNF];
#pragma unroll
            for (int i = 0; i < 2; i++)
                wmma::load_matrix_sync(af[i], Asm + (wm * 32 + i * 16) * LDA + kk, LDA);
#pragma unroll
            for (int j = 0; j < WNF; j++)
                wmma::load_matrix_sync(bf[j], Bsm + kk * LDB + wn * (BN / 4) + j * 16, LDB);
#pragma unroll
            for (int i = 0; i < 2; i++)
#pragma unroll
                for (int j = 0; j < WNF; j++)
                    wmma::mma_sync(acc[i][j], af[i], bf[j], acc[i][j]);
        }

        if (A_F32) {
            if (ks + 1 < KSTEPS) {   // STS A(ks+1) -> visible after next sync
                __half* An = reinterpret_cast<__half*>(smem + ((ks + 1) % 4) * STGB);
#pragma unroll
                for (int r = 0; r < 2; r++) {
                    int row = ar + r * 32;
                    __half hx[4] = {__float2half_rn(raf[r].x), __float2half_rn(raf[r].y),
                                    __float2half_rn(raf[r].z), __float2half_rn(raf[r].w)};
                    *reinterpret_cast<uint2*>(An + row * LDA + ac4) =
                        *reinterpret_cast<uint2*>(hx);
                }
            }
            if (ks + 2 < KSTEPS) {   // LDG A(ks+2)
                const int k0n = (ks + 2) * BK;
#pragma unroll
                for (int r = 0; r < 2; r++) {
                    int row = ar + r * 32;
                    raf[r] = *reinterpret_cast<const float4*>(
                        Af + (size_t)(m0 + row) * K + k0n + ac4);
                }
            }
        }
    }

    // ---- epilogue: 2 passes of 32 rows via sC (aliases stage smem) ----
#pragma unroll
    for (int pass = 0; pass < 2; pass++) {
        __syncthreads();
        if (wm == pass) {
#pragma unroll
            for (int i = 0; i < 2; i++)
#pragma unroll
                for (int j = 0; j < WNF; j++)
                    wmma::store_matrix_sync(&sC[(i * 16) * BN + wn * (BN / 4) + j * 16],
                                            acc[i][j], BN, wmma::mem_row_major);
        }
        __syncthreads();
        int rbase = m0 + pass * 32;
        if constexpr (MODE <= 1 || MODE == 3) {
            __half* C = (MODE == 0) ? g_e1 : (MODE == 1) ? g_e2 : g_proj_h;
#pragma unroll
            for (int r = 0; r < (32 * BN / 2) / 256; r++) {
                int idx = tid + r * 256;
                int row = idx / (BN / 2), c2 = (idx % (BN / 2)) * 2;
                __half2 hv = __floats2half2_rn(sC[row * BN + c2], sC[row * BN + c2 + 1]);
                *reinterpret_cast<__half2*>(C + (size_t)(rbase + row) * NW + n0 + c2) = hv;
            }
        } else if constexpr (MODE == 2) {
#pragma unroll
            for (int r = 0; r < 8; r++) {
                int idx = tid + r * 256;
                int row = idx >> 6, c4 = (idx & 63) * 4;
                float4 v = *reinterpret_cast<const float4*>(&sC[row * BN + c4]);
                v.x = fmaxf(v.x, 0.f); v.y = fmaxf(v.y, 0.f);
                v.z = fmaxf(v.z, 0.f); v.w = fmaxf(v.w, 0.f);
                size_t o = (size_t)(rbase + row) * 256 + c4;
                *reinterpret_cast<float4*>(g_out + o) = v;
                *reinterpret_cast<__half2*>(g_out_h + o)     = __floats2half2_rn(v.x, v.y);
                *reinterpret_cast<__half2*>(g_out_h + o + 2) = __floats2half2_rn(v.z, v.w);
            }
        } else { // MODE 4
#pragma unroll
            for (int r = 0; r < (32 * BN / 4) / 256; r++) {
                int idx = tid + r * 256;
                int row = idx / (BN / 4), c4 = (idx % (BN / 4)) * 4;
                *reinterpret_cast<float4*>(g_gcn + (size_t)(rbase + row) * 256 + n0 + c4) =
                    *reinterpret_cast<const float4*>(&sC[row * BN + c4]);
            }
        }
    }
}

static inline int gemm_smem_bytes(int BN) {
    int stgb = (64 * 40 + 32 * (BN + 8)) * 2;
    int pipe = 4 * stgb;
    int epil = 32 * BN * 4;
    return pipe > epil ? pipe : epil;
}

// ---------------------------------------------------------------------------
// ta = text @ align_lin (fp32; precision-critical for softmax logits)
// ---------------------------------------------------------------------------
__global__ __launch_bounds__(256) void ta_kernel(const float* __restrict__ text,
                                                 const float* __restrict__ alin)
{
    __shared__ float sT[8][260];
    const int r0 = blockIdx.x * 8;
    for (int idx = threadIdx.x; idx < 8 * 64; idx += 256) {
        int r = idx >> 6, c4 = (idx & 63) * 4;
        *reinterpret_cast<float4*>(&sT[r][c4]) =
            *reinterpret_cast<const float4*>(text + (size_t)(r0 + r) * 256 + c4);
    }
    __syncthreads();
    const int n = threadIdx.x;
    float acc[8];
#pragma unroll
    for (int r = 0; r < 8; r++) acc[r] = 0.f;
    for (int k = 0; k < 256; k += 4) {
        float a0 = alin[(size_t)k * 256 + n];
        float a1 = alin[(size_t)(k + 1) * 256 + n];
        float a2 = alin[(size_t)(k + 2) * 256 + n];
        float a3 = alin[(size_t)(k + 3) * 256 + n];
#pragma unroll
        for (int r = 0; r < 8; r++) {
            float4 t = *reinterpret_cast<const float4*>(&sT[r][k]);
            acc[r] += t.x * a0 + t.y * a1 + t.z * a2 + t.w * a3;
        }
    }
#pragma unroll
    for (int r = 0; r < 8; r++)
        g_ta[(size_t)(r0 + r) * 256 + n] = acc[r];
}

// ---------------------------------------------------------------------------
// Self-alignment attention (fp32): block per (b,i)
// ---------------------------------------------------------------------------
__global__ __launch_bounds__(256) void attn_kernel(const float* __restrict__ text,
                                                   const float* __restrict__ tmask,
                                                   const float* __restrict__ align_bias,
                                                   float* __restrict__ outp)
{
    __shared__ float slog[128];
    __shared__ float s_red[2];
    const int row = blockIdx.x;
    const int b = row >> 7;
    const int tid = threadIdx.x, w = tid >> 5, lane = tid & 31;

    float ta0[8];
    {
        const float* tarow = g_ta + (size_t)row * 256 + lane * 8;
        float4 q0 = *reinterpret_cast<const float4*>(tarow);
        float4 q1 = *reinterpret_cast<const float4*>(tarow + 4);
        ta0[0] = q0.x; ta0[1] = q0.y; ta0[2] = q0.z; ta0[3] = q0.w;
        ta0[4] = q1.x; ta0[5] = q1.y; ta0[6] = q1.z; ta0[7] = q1.w;
    }
    for (int j = w; j < 128; j += 8) {
        const float* tr = text + (size_t)(b * 128 + j) * 256 + lane * 8;
        float4 t0 = *reinterpret_cast<const float4*>(tr);
        float4 t1 = *reinterpret_cast<const float4*>(tr + 4);
        float d = ta0[0] * t0.x + ta0[1] * t0.y + ta0[2] * t0.z + ta0[3] * t0.w
                + ta0[4] * t1.x + ta0[5] * t1.y + ta0[6] * t1.z + ta0[7] * t1.w;
#pragma unroll
        for (int o = 16; o > 0; o >>= 1) d += __shfl_xor_sync(0xffffffffu, d, o);
        if (lane == 0)
            slog[j] = d + (1.0f - tmask[b * 128 + j]) * -1e20f;
    }
    __syncthreads();
    if (w == 0) {
        float m = fmaxf(fmaxf(slog[lane], slog[lane + 32]),
                        fmaxf(slog[lane + 64], slog[lane + 96]));
#pragma unroll
        for (int o = 16; o > 0; o >>= 1) m = fmaxf(m, __shfl_xor_sync(0xffffffffu, m, o));
        if (lane == 0) s_red[0] = m;
    }
    __syncthreads();
    float smax = s_red[0];
    if (tid < 128) slog[tid] = expf(slog[tid] - smax);
    __syncthreads();
    if (w == 0) {
        float s = slog[lane] + slog[lane + 32] + slog[lane + 64] + slog[lane + 96];
#pragma unroll
        for (int o = 16; o > 0; o >>= 1) s += __shfl_xor_sync(0xffffffffu, s, o);
        if (lane == 0) s_red[1] = s;
    }
    __syncthreads();
    float inv = 1.0f / s_red[1];
    const int c = tid;
    float acc = 0.f;
    for (int j = 0; j < 128; j++)
        acc += slog[j] * text[(size_t)(b * 128 + j) * 256 + c];
    outp[262144 + (size_t)row * 256 + c] = acc * inv * tmask[row] + align_bias[c];
}

// ---------------------------------------------------------------------------
// Gate/accumulate: block per (b,i), warp per j (16 j's each of 8 warps).
// ---------------------------------------------------------------------------
__global__ __launch_bounds__(256) void accum_kernel(
    const float* __restrict__ adj1, const float* __restrict__ adj2,
    const float* __restrict__ w1g,  const float* __restrict__ w2g,
    const float* __restrict__ b1g,  const float* __restrict__ b2g)
{
    __shared__ float s1[8][256];
    __shared__ float s2[8][256];
    __shared__ float sadj[8][2];
    const int row = blockIdx.x;
    const int b = row >> 7;
    const int tid = threadIdx.x, w = tid >> 5, lane = tid & 31;
    const int cbase = lane * 8;

    float a1[8], a2[8], w1[8], w2[8], acc1[8], acc2[8];
    {
        const __half* ph = g_proj_h + (size_t)row * 1536;
        uint4 ua = *reinterpret_cast<const uint4*>(ph + cbase);
        uint4 ub = *reinterpret_cast<const uint4*>(ph + 512 + cbase);
        unpack8(ua, a1); unpack8(ub, a2);
    }
#pragma unroll
    for (int k = 0; k < 8; k++) {
        w1[k] = w1g[cbase + k]; w2[k] = w2g[cbase + k];
        acc1[k] = 0.f; acc2[k] = 0.f;
    }
    const float fb1 = b1g[0], fb2 = b2g[0];
    float as1 = 0.f, as2 = 0.f;

    for (int j = w; j < 128; j += 8) {
        const __half* e1p = g_e1 + ((size_t)row * 128 + j) * 512;
        const __half* e2p = g_e2 + ((size_t)row * 128 + j) * 512;
        const __half* pj  = g_proj_h + (size_t)(b * 128 + j) * 1536;
        uint4 uf1 = *reinterpret_cast<const uint4*>(e1p + cbase);
        uint4 uc1 = *reinterpret_cast<const uint4*>(e1p + 256 + cbase);
        uint4 uf2 = *reinterpret_cast<const uint4*>(e2p + cbase);
        uint4 uc2 = *reinterpret_cast<const uint4*>(e2p + 256 + cbase);
        uint4 ub1 = *reinterpret_cast<const uint4*>(pj + 256 + cbase);
        uint4 ub2 = *reinterpret_cast<const uint4*>(pj + 768 + cbase);
        uint4 uu1 = *reinterpret_cast<const uint4*>(pj + 1024 + cbase);
        uint4 uu2 = *reinterpret_cast<const uint4*>(pj + 1280 + cbase);
        float f1[8], c1[8], f2[8], c2[8], bb1[8], bb2[8], u1[8], u2[8];
        unpack8(uf1, f1); unpack8(uc1, c1);
        unpack8(uf2, f2); unpack8(uc2, c2);
        unpack8(ub1, bb1); unpack8(ub2, bb2);
        unpack8(uu1, u1);  unpack8(uu2, u2);

        float d1 = 0.f, d2 = 0.f;
#pragma unroll
        for (int k = 0; k < 8; k++) {
            d1 += w1[k] * fmaxf(a1[k] + bb1[k] + c1[k], 0.f);
            d2 += w2[k] * fmaxf(a2[k] + bb2[k] + c2[k], 0.f);
        }
#pragma unroll
        for (int o = 16; o > 0; o >>= 1) {
            d1 += __shfl_xor_sync(0xffffffffu, d1, o);
            d2 += __shfl_xor_sync(0xffffffffu, d2, o);
        }
        float av1 = adj1[(size_t)row * 128 + j];
        float av2 = adj2[(size_t)row * 128 + j];
        float g1 = av1 / (1.f + __expf(-(d1 + fb1)));
        float g2 = av2 / (1.f + __expf(-(d2 + fb2)));
        as1 += av1; as2 += av2;
#pragma unroll
        for (int k = 0; k < 8; k++) {
            acc1[k] += g1 * fmaxf(u1[k] + f1[k], 0.f);
            acc2[k] += g2 * fmaxf(u2[k] + f2[k], 0.f);
        }
    }
#pragma unroll
    for (int k = 0; k < 8; k++) {
        s1[w][cbase + k] = acc1[k];
        s2[w][cbase + k] = acc2[k];
    }
    if (lane == 0) { sadj[w][0] = as1; sadj[w][1] = as2; }
    __syncthreads();
    const int c = tid;
    float t1 = 0.f, t2 = 0.f, den1 = 1.f, den2 = 1.f;
#pragma unroll
    for (int ww = 0; ww < 8; ww++) {
        t1 += s1[ww][c]; t2 += s2[ww][c];
        den1 += sadj[ww][0]; den2 += sadj[ww][1];
    }
    g_acc_h[(size_t)row * 512 + c]       = __float2half_rn(t1 / den1);
    g_acc_h[(size_t)row * 512 + 256 + c] = __float2half_rn(t2 / den2);
}

// ---------------------------------------------------------------------------
// out = layernorm(relu(g_gcn) + out + bias); refresh g_out / g_out_h
// ---------------------------------------------------------------------------
__global__ __launch_bounds__(256) void ln_kernel(
    const float* __restrict__ bias, const float* __restrict__ gamma,
    const float* __restrict__ beta, float* __restrict__ outp, int final_it)
{
    __shared__ float s[8];
    const int row = blockIdx.x, c = threadIdx.x;
    const int w = c >> 5, lane = c & 31;
    float v = fmaxf(g_gcn[(size_t)row * 256 + c], 0.f)
            + g_out[(size_t)row * 256 + c] + bias[c];
    float t = v;
#pragma unroll
    for (int o = 16; o > 0; o >>= 1) t += __shfl_xor_sync(0xffffffffu, t, o);
    if (lane == 0) s[w] = t;
    __syncthreads();
    float m = 0.f;
#pragma unroll
    for (int i = 0; i < 8; i++) m += s[i];
    m *= (1.f / 256.f);
    __syncthreads();
    float d = v - m;
    t = d * d;
#pragma unroll
    for (int o = 16; o > 0; o >>= 1) t += __shfl_xor_sync(0xffffffffu, t, o);
    if (lane == 0) s[w] = t;
    __syncthreads();
    float var = 0.f;
#pragma unroll
    for (int i = 0; i < 8; i++) var += s[i];
    var *= (1.f / 256.f);
    float r = rsqrtf(var + 1e-5f);
    float o = d * r * gamma[c] + beta[c];
    g_out[(size_t)row * 256 + c] = o;
    g_out_h[(size_t)row * 256 + c] = __float2half_rn(o);
    if (final_it) outp[(size_t)row * 256 + c] = o;
}

// ---------------------------------------------------------------------------
extern "C" void kernel_launch(void* const* d_in, const int* in_sizes, int n_in,
                              void* d_out, int out_size)
{
    const float* text       = (const float*)d_in[0];
    const float* adj1       = (const float*)d_in[1];
    const float* adj2       = (const float*)d_in[2];
    const float* edge1      = (const float*)d_in[3];
    const float* edge2      = (const float*)d_in[4];
    const float* textmask   = (const float*)d_in[5];
    const float* weight     = (const float*)d_in[6];
    const float* bias       = (const float*)d_in[7];
    const float* gamma      = (const float*)d_in[8];
    const float* beta       = (const float*)d_in[9];
    const float* fuse1_w    = (const float*)d_in[10];
    const float* fuse2_w    = (const float*)d_in[11];
    const float* fc3_w      = (const float*)d_in[12];
    const float* fc1_w0     = (const float*)d_in[13];
    const float* fc1_w1     = (const float*)d_in[14];
    const float* fc1_b1     = (const float*)d_in[15];
    const float* fc2_w0     = (const float*)d_in[16];
    const float* fc2_w1     = (const float*)d_in[17];
    const float* fc2_b1     = (const float*)d_in[18];
    const float* align_lin  = (const float*)d_in[19];
    const float* align_bias = (const float*)d_in[20];
    float* outp = (float*)d_out;

    const int smb256 = gemm_smem_bytes(256);   // 88064
    const int smb64  = gemm_smem_bytes(64);    // 38912
    cudaFuncSetAttribute(gemm_kernel<0>, cudaFuncAttributeMaxDynamicSharedMemorySize, smb256);
    cudaFuncSetAttribute(gemm_kernel<1>, cudaFuncAttributeMaxDynamicSharedMemorySize, smb256);
    cudaFuncSetAttribute(gemm_kernel<2>, cudaFuncAttributeMaxDynamicSharedMemorySize, smb256);
    cudaFuncSetAttribute(gemm_kernel<3>, cudaFuncAttributeMaxDynamicSharedMemorySize, smb256);
    cudaFuncSetAttribute(gemm_kernel<4>, cudaFuncAttributeMaxDynamicSharedMemorySize, smb64);

    prep_kernel<<<1024, 256>>>(fuse1_w, fuse2_w, fc1_w0, fc2_w0, fc3_w, weight, text);

    // self-alignment path (independent)
    ta_kernel<<<128, 256>>>(text, align_lin);
    attn_kernel<<<1024, 256>>>(text, textmask, align_bias, outp);

    // edge projections
    gemm_kernel<0><<<dim3(2, 2048), 256, smb256>>>(edge1);
    gemm_kernel<1><<<dim3(2, 2048), 256, smb256>>>(edge2);

    // out = relu(text @ weight)
    gemm_kernel<2><<<dim3(1, 16), 256, smb256>>>(nullptr);

    for (int it = 0; it < 3; it++) {
        gemm_kernel<3><<<dim3(6, 16), 256, smb256>>>(nullptr);
        accum_kernel<<<1024, 256>>>(adj1, adj2, fc1_w1, fc2_w1, fc1_b1, fc2_b1);
        gemm_kernel<4><<<dim3(4, 16), 256, smb64>>>(nullptr);
        ln_kernel<<<1024, 256>>>(bias, gamma, beta, outp, it == 2 ? 1 : 0);
    }
}